// round 3
// baseline (speedup 1.0000x reference)
#include <cuda_runtime.h>
#include <math.h>

#define NB 2
#define NL 2048
#define NDM 1024
#define NH 16
#define NDH 64
#define NC 8
#define NPC 256
#define NG 16

// ---------------- scratch (device globals; no allocation allowed) -------------
__device__ float g_qkv[NB * NL * 3 * NDM];   // (B, L, 3, H, DH)
__device__ float g_qT[NB * NH * NL * NDH];   // (B, H, L, DH)
__device__ float g_kT[NB * NH * NL * NDH];
__device__ float g_vT[NB * NH * NL * NDH];
__device__ float g_oT[NB * NH * NL * NDH];
__device__ float g_oTok[NB * NL * NDM];      // (B, L, H*DH)
__device__ float g_P [NB * NC * 16];
__device__ float g_Pi[NB * NC * 16];
__device__ float g_Dt[NPC * NG * 4];         // (p, g) -> ca, sa, cb, sb

// ---------------- per-camera P and P^{-1} -------------------------------------
__global__ void prope_mats(const float* __restrict__ vm, const float* __restrict__ Km) {
    int i = threadIdx.x;
    if (i >= NB * NC) return;
    const float* V = vm + i * 16;
    const float* Kc = Km + i * 9;
    double P[16];
    for (int r = 0; r < 3; r++)
        for (int j = 0; j < 4; j++) {
            double s = 0.0;
            for (int m = 0; m < 3; m++) s += (double)Kc[r * 3 + m] * (double)V[m * 4 + j];
            P[r * 4 + j] = s;
        }
    P[12] = V[12]; P[13] = V[13]; P[14] = V[14]; P[15] = V[15];
    for (int t = 0; t < 16; t++) g_P[i * 16 + t] = (float)P[t];

    // P = [[A, b],[0,1]] -> P^-1 = [[A^-1, -A^-1 b],[0,1]]
    double a00 = P[0], a01 = P[1], a02 = P[2];
    double a10 = P[4], a11 = P[5], a12 = P[6];
    double a20 = P[8], a21 = P[9], a22 = P[10];
    double c00 =  a11 * a22 - a12 * a21;
    double c01 = -(a10 * a22 - a12 * a20);
    double c02 =  a10 * a21 - a11 * a20;
    double det = a00 * c00 + a01 * c01 + a02 * c02;
    double id = 1.0 / det;
    double i00 = c00 * id;
    double i01 = (a02 * a21 - a01 * a22) * id;
    double i02 = (a01 * a12 - a02 * a11) * id;
    double i10 = c01 * id;
    double i11 = (a00 * a22 - a02 * a20) * id;
    double i12 = (a02 * a10 - a00 * a12) * id;
    double i20 = c02 * id;
    double i21 = (a01 * a20 - a00 * a21) * id;
    double i22 = (a00 * a11 - a01 * a10) * id;
    double b0 = P[3], b1 = P[7], b2 = P[11];
    double Pi[16] = { i00, i01, i02, -(i00 * b0 + i01 * b1 + i02 * b2),
                      i10, i11, i12, -(i10 * b0 + i11 * b1 + i12 * b2),
                      i20, i21, i22, -(i20 * b0 + i21 * b1 + i22 * b2),
                      0.0, 0.0, 0.0, 1.0 };
    for (int t = 0; t < 16; t++) g_Pi[i * 16 + t] = (float)Pi[t];
}

// ---------------- RoPE rotation table -----------------------------------------
__global__ void prope_dtab() {
    int idx = blockIdx.x * blockDim.x + threadIdx.x;
    if (idx >= NPC * NG) return;
    int p = idx >> 4, g = idx & 15;
    float u = ((p & 15) + 0.5f) * 16.0f;   // IMG_W / PATCHES_X = 16
    float v = ((p >> 4) + 0.5f) * 16.0f;
    float freq = (float)pow(10000.0, -(double)g / 16.0);
    float tu = u * freq;
    float tv = v * freq;
    g_Dt[idx * 4 + 0] = (float)cos((double)tu);
    g_Dt[idx * 4 + 1] = (float)sin((double)tu);
    g_Dt[idx * 4 + 2] = (float)cos((double)tv);
    g_Dt[idx * 4 + 3] = (float)sin((double)tv);
}

// ---------------- SGEMM: C[m][n] = sum_k A[m][k] * B[n][k] --------------------
// BM = BN = 128, BK = 8, 256 threads, 8x8 microtile.
__device__ __forceinline__ void gemm_body(const float* __restrict__ A,
                                          const float* __restrict__ Bw,
                                          float* __restrict__ C, int N, int K) {
    __shared__ float As[8][128];
    __shared__ float Bs[8][128];
    const int tid = threadIdx.x;
    const int m0 = blockIdx.y * 128;
    const int n0 = blockIdx.x * 128;
    const int tx = tid & 15, ty = tid >> 4;
    const int lr = tid >> 1, lc = (tid & 1) * 4;

    float acc[8][8];
#pragma unroll
    for (int i = 0; i < 8; i++)
#pragma unroll
        for (int j = 0; j < 8; j++) acc[i][j] = 0.f;

    for (int k0 = 0; k0 < K; k0 += 8) {
        float4 av = *(const float4*)(A  + (size_t)(m0 + lr) * K + k0 + lc);
        float4 bv = *(const float4*)(Bw + (size_t)(n0 + lr) * K + k0 + lc);
        __syncthreads();
        As[lc + 0][lr] = av.x; As[lc + 1][lr] = av.y; As[lc + 2][lr] = av.z; As[lc + 3][lr] = av.w;
        Bs[lc + 0][lr] = bv.x; Bs[lc + 1][lr] = bv.y; Bs[lc + 2][lr] = bv.z; Bs[lc + 3][lr] = bv.w;
        __syncthreads();
#pragma unroll
        for (int k = 0; k < 8; k++) {
            float ar[8], br[8];
            *(float4*)(ar)     = *(const float4*)&As[k][ty * 8];
            *(float4*)(ar + 4) = *(const float4*)&As[k][ty * 8 + 4];
            *(float4*)(br)     = *(const float4*)&Bs[k][tx * 8];
            *(float4*)(br + 4) = *(const float4*)&Bs[k][tx * 8 + 4];
#pragma unroll
            for (int i = 0; i < 8; i++)
#pragma unroll
                for (int j = 0; j < 8; j++) acc[i][j] += ar[i] * br[j];
        }
    }
#pragma unroll
    for (int i = 0; i < 8; i++) {
        float4 v0 = make_float4(acc[i][0], acc[i][1], acc[i][2], acc[i][3]);
        float4 v1 = make_float4(acc[i][4], acc[i][5], acc[i][6], acc[i][7]);
        *(float4*)(C + (size_t)(m0 + ty * 8 + i) * N + n0 + tx * 8)     = v0;
        *(float4*)(C + (size_t)(m0 + ty * 8 + i) * N + n0 + tx * 8 + 4) = v1;
    }
}

__global__ void __launch_bounds__(256) k_gemm_qkv(const float* __restrict__ x,
                                                  const float* __restrict__ w) {
    gemm_body(x, w, g_qkv, 3 * NDM, NDM);
}
__global__ void __launch_bounds__(256) k_gemm_proj(const float* __restrict__ w,
                                                   float* __restrict__ out) {
    gemm_body(g_oTok, w, out, NDM, NDM);
}

// ---------------- apply Mq / Mkv to q, k, v ------------------------------------
__global__ void k_transform_qkv() {
    int idx = blockIdx.x * blockDim.x + threadIdx.x;
    if (idx >= NB * NH * NL * NG) return;
    int g = idx & 15;
    int l = (idx >> 4) & (NL - 1);
    int h = (idx >> 15) & 15;
    int b = idx >> 19;
    int c = l >> 8, p = l & 255;
    const float* Pm = g_P  + (b * NC + c) * 16;
    const float* Pi = g_Pi + (b * NC + c) * 16;
    float4 dv = *(const float4*)(g_Dt + (p * NG + g) * 4);
    float ca = dv.x, sa = dv.y, cb = dv.z, sb = dv.w;

    size_t base = ((size_t)(b * NL + l) * 3) * NDM + h * NDH + g * 4;
    size_t obase = ((size_t)(b * NH + h) * NL + l) * NDH + g * 4;

    // q: P^{-T} (D q)
    {
        float4 t = *(const float4*)(g_qkv + base);
        float d0 = ca * t.x - sa * t.y, d1 = sa * t.x + ca * t.y;
        float d2 = cb * t.z - sb * t.w, d3 = sb * t.z + cb * t.w;
        float4 o;
        o.x = Pi[0] * d0 + Pi[4] * d1 + Pi[8]  * d2 + Pi[12] * d3;
        o.y = Pi[1] * d0 + Pi[5] * d1 + Pi[9]  * d2 + Pi[13] * d3;
        o.z = Pi[2] * d0 + Pi[6] * d1 + Pi[10] * d2 + Pi[14] * d3;
        o.w = Pi[3] * d0 + Pi[7] * d1 + Pi[11] * d2 + Pi[15] * d3;
        *(float4*)(g_qT + obase) = o;
    }
    // k: P (D k)
    {
        float4 t = *(const float4*)(g_qkv + base + NDM);
        float d0 = ca * t.x - sa * t.y, d1 = sa * t.x + ca * t.y;
        float d2 = cb * t.z - sb * t.w, d3 = sb * t.z + cb * t.w;
        float4 o;
        o.x = Pm[0]  * d0 + Pm[1]  * d1 + Pm[2]  * d2 + Pm[3]  * d3;
        o.y = Pm[4]  * d0 + Pm[5]  * d1 + Pm[6]  * d2 + Pm[7]  * d3;
        o.z = Pm[8]  * d0 + Pm[9]  * d1 + Pm[10] * d2 + Pm[11] * d3;
        o.w = Pm[12] * d0 + Pm[13] * d1 + Pm[14] * d2 + Pm[15] * d3;
        *(float4*)(g_kT + obase) = o;
    }
    // v: P (D v)
    {
        float4 t = *(const float4*)(g_qkv + base + 2 * NDM);
        float d0 = ca * t.x - sa * t.y, d1 = sa * t.x + ca * t.y;
        float d2 = cb * t.z - sb * t.w, d3 = sb * t.z + cb * t.w;
        float4 o;
        o.x = Pm[0]  * d0 + Pm[1]  * d1 + Pm[2]  * d2 + Pm[3]  * d3;
        o.y = Pm[4]  * d0 + Pm[5]  * d1 + Pm[6]  * d2 + Pm[7]  * d3;
        o.z = Pm[8]  * d0 + Pm[9]  * d1 + Pm[10] * d2 + Pm[11] * d3;
        o.w = Pm[12] * d0 + Pm[13] * d1 + Pm[14] * d2 + Pm[15] * d3;
        *(float4*)(g_vT + obase) = o;
    }
}

// ---------------- flash attention (fp32, BM=64, BN=64) -------------------------
// Q/K/S tiles use stride FS=65 (scalar access only).
// V tile uses stride FSV=72: 72*4 = 288 bytes, 16B-aligned rows for LDS.128,
// and 72 mod 32 = 8 gives a bank rotation per row.
#define FS 65
#define FSV 72
#define FLASH_SMEM ((3 * 64 * FS + 64 * FSV) * 4)

__global__ void __launch_bounds__(256) k_flash() {
    extern __shared__ float fsh[];
    float* Qs = fsh;
    float* Ks = fsh + 64 * FS;
    float* Ss = fsh + 2 * 64 * FS;
    float* Vs = fsh + 3 * 64 * FS;

    const int tid = threadIdx.x;
    const int bh = blockIdx.y;
    const int q0 = blockIdx.x * 64;
    const float* Qg = g_qT + (size_t)bh * NL * NDH;
    const float* Kg = g_kT + (size_t)bh * NL * NDH;
    const float* Vg = g_vT + (size_t)bh * NL * NDH;

    for (int i = tid; i < 64 * 16; i += 256) {
        int r = i >> 4, cidx = (i & 15) << 2;
        float4 t = *(const float4*)(Qg + (size_t)(q0 + r) * NDH + cidx);
        Qs[r * FS + cidx]     = t.x; Qs[r * FS + cidx + 1] = t.y;
        Qs[r * FS + cidx + 2] = t.z; Qs[r * FS + cidx + 3] = t.w;
    }

    const int rg = tid >> 3;    // rows 2*rg, 2*rg+1
    const int cg = tid & 7;     // cols cg + 8*j
    const int db = cg * 8;      // output dims db..db+7
    float mrow[2] = { -1e30f, -1e30f };
    float lrow[2] = { 0.f, 0.f };
    float acc[2][8];
#pragma unroll
    for (int rr = 0; rr < 2; rr++)
#pragma unroll
        for (int d = 0; d < 8; d++) acc[rr][d] = 0.f;

    for (int n0 = 0; n0 < NL; n0 += 64) {
        __syncthreads();
        for (int i = tid; i < 64 * 16; i += 256) {
            int r = i >> 4, cidx = (i & 15) << 2;
            float4 kt = *(const float4*)(Kg + (size_t)(n0 + r) * NDH + cidx);
            Ks[r * FS + cidx]     = kt.x; Ks[r * FS + cidx + 1] = kt.y;
            Ks[r * FS + cidx + 2] = kt.z; Ks[r * FS + cidx + 3] = kt.w;
            float4 vt = *(const float4*)(Vg + (size_t)(n0 + r) * NDH + cidx);
            *(float4*)&Vs[r * FSV + cidx] = vt;
        }
        __syncthreads();

        // S = Q K^T * scale, 2x8 microtile per thread
        float s[2][8];
#pragma unroll
        for (int rr = 0; rr < 2; rr++)
#pragma unroll
            for (int j = 0; j < 8; j++) s[rr][j] = 0.f;
        const float* q0p = Qs + (2 * rg) * FS;
        const float* q1p = Qs + (2 * rg + 1) * FS;
        for (int k = 0; k < 64; k++) {
            float qa = q0p[k];
            float qb = q1p[k];
#pragma unroll
            for (int j = 0; j < 8; j++) {
                float kv = Ks[(cg + 8 * j) * FS + k];
                s[0][j] += qa * kv;
                s[1][j] += qb * kv;
            }
        }
        float mt0 = -1e30f, mt1 = -1e30f;
#pragma unroll
        for (int j = 0; j < 8; j++) {
            s[0][j] *= 0.125f; s[1][j] *= 0.125f;
            mt0 = fmaxf(mt0, s[0][j]);
            mt1 = fmaxf(mt1, s[1][j]);
        }
#pragma unroll
        for (int off = 1; off < 8; off <<= 1) {
            mt0 = fmaxf(mt0, __shfl_xor_sync(0xffffffffu, mt0, off));
            mt1 = fmaxf(mt1, __shfl_xor_sync(0xffffffffu, mt1, off));
        }
        float mn0 = fmaxf(mrow[0], mt0);
        float mn1 = fmaxf(mrow[1], mt1);
        float al0 = __expf(mrow[0] - mn0);
        float al1 = __expf(mrow[1] - mn1);
        float lp0 = 0.f, lp1 = 0.f;
#pragma unroll
        for (int j = 0; j < 8; j++) {
            float p0 = __expf(s[0][j] - mn0);
            float p1 = __expf(s[1][j] - mn1);
            lp0 += p0; lp1 += p1;
            Ss[(2 * rg)     * FS + cg + 8 * j] = p0;
            Ss[(2 * rg + 1) * FS + cg + 8 * j] = p1;
        }
#pragma unroll
        for (int off = 1; off < 8; off <<= 1) {
            lp0 += __shfl_xor_sync(0xffffffffu, lp0, off);
            lp1 += __shfl_xor_sync(0xffffffffu, lp1, off);
        }
        lrow[0] = lrow[0] * al0 + lp0;
        lrow[1] = lrow[1] * al1 + lp1;
        mrow[0] = mn0; mrow[1] = mn1;
#pragma unroll
        for (int d = 0; d < 8; d++) { acc[0][d] *= al0; acc[1][d] *= al1; }
        __syncwarp();

        // O += P V
        const float* s0p = Ss + (2 * rg) * FS;
        const float* s1p = Ss + (2 * rg + 1) * FS;
        for (int j = 0; j < 64; j++) {
            float p0 = s0p[j];
            float p1 = s1p[j];
            float4 va = *(const float4*)&Vs[j * FSV + db];
            float4 vb = *(const float4*)&Vs[j * FSV + db + 4];
            acc[0][0] += p0 * va.x; acc[0][1] += p0 * va.y;
            acc[0][2] += p0 * va.z; acc[0][3] += p0 * va.w;
            acc[0][4] += p0 * vb.x; acc[0][5] += p0 * vb.y;
            acc[0][6] += p0 * vb.z; acc[0][7] += p0 * vb.w;
            acc[1][0] += p1 * va.x; acc[1][1] += p1 * va.y;
            acc[1][2] += p1 * va.z; acc[1][3] += p1 * va.w;
            acc[1][4] += p1 * vb.x; acc[1][5] += p1 * vb.y;
            acc[1][6] += p1 * vb.z; acc[1][7] += p1 * vb.w;
        }
    }

    float il0 = 1.f / lrow[0];
    float il1 = 1.f / lrow[1];
    float* Og = g_oT + (size_t)bh * NL * NDH;
    float4 o0a = make_float4(acc[0][0] * il0, acc[0][1] * il0, acc[0][2] * il0, acc[0][3] * il0);
    float4 o0b = make_float4(acc[0][4] * il0, acc[0][5] * il0, acc[0][6] * il0, acc[0][7] * il0);
    float4 o1a = make_float4(acc[1][0] * il1, acc[1][1] * il1, acc[1][2] * il1, acc[1][3] * il1);
    float4 o1b = make_float4(acc[1][4] * il1, acc[1][5] * il1, acc[1][6] * il1, acc[1][7] * il1);
    *(float4*)(Og + (size_t)(q0 + 2 * rg) * NDH + db)         = o0a;
    *(float4*)(Og + (size_t)(q0 + 2 * rg) * NDH + db + 4)     = o0b;
    *(float4*)(Og + (size_t)(q0 + 2 * rg + 1) * NDH + db)     = o1a;
    *(float4*)(Og + (size_t)(q0 + 2 * rg + 1) * NDH + db + 4) = o1b;
}

// ---------------- apply Mo to o, write token-major -----------------------------
__global__ void k_transform_o() {
    int idx = blockIdx.x * blockDim.x + threadIdx.x;
    if (idx >= NB * NH * NL * NG) return;
    int g = idx & 15;
    int l = (idx >> 4) & (NL - 1);
    int h = (idx >> 15) & 15;
    int b = idx >> 19;
    int c = l >> 8, p = l & 255;
    const float* Pi = g_Pi + (b * NC + c) * 16;
    float4 dv = *(const float4*)(g_Dt + (p * NG + g) * 4);
    float ca = dv.x, sa = dv.y, cb = dv.z, sb = dv.w;

    float4 t = *(const float4*)(g_oT + ((size_t)(b * NH + h) * NL + l) * NDH + g * 4);
    float z0 = Pi[0]  * t.x + Pi[1]  * t.y + Pi[2]  * t.z + Pi[3]  * t.w;
    float z1 = Pi[4]  * t.x + Pi[5]  * t.y + Pi[6]  * t.z + Pi[7]  * t.w;
    float z2 = Pi[8]  * t.x + Pi[9]  * t.y + Pi[10] * t.z + Pi[11] * t.w;
    float z3 = Pi[12] * t.x + Pi[13] * t.y + Pi[14] * t.z + Pi[15] * t.w;
    float4 o;
    o.x =  ca * z0 + sa * z1;
    o.y = -sa * z0 + ca * z1;
    o.z =  cb * z2 + sb * z3;
    o.w = -sb * z2 + cb * z3;
    *(float4*)(g_oTok + (size_t)(b * NL + l) * NDM + h * NDH + g * 4) = o;
}

// ---------------- launch --------------------------------------------------------
extern "C" void kernel_launch(void* const* d_in, const int* in_sizes, int n_in,
                              void* d_out, int out_size) {
    (void)in_sizes; (void)n_in; (void)out_size;
    const float* x     = (const float*)d_in[0];
    const float* vm    = (const float*)d_in[1];
    const float* Km    = (const float*)d_in[2];
    const float* wqkv  = (const float*)d_in[3];
    const float* wproj = (const float*)d_in[4];
    float* out = (float*)d_out;

    cudaFuncSetAttribute(k_flash, cudaFuncAttributeMaxDynamicSharedMemorySize, FLASH_SMEM);

    prope_mats<<<1, 32>>>(vm, Km);
    prope_dtab<<<16, 256>>>();
    k_gemm_qkv<<<dim3(3 * NDM / 128, NB * NL / 128), 256>>>(x, wqkv);
    k_transform_qkv<<<(NB * NH * NL * NG) / 256, 256>>>();
    k_flash<<<dim3(NL / 64, NB * NH), 256, FLASH_SMEM>>>();
    k_transform_o<<<(NB * NH * NL * NG) / 256, 256>>>();
    k_gemm_proj<<<dim3(NDM / 128, NB * NL / 128), 256>>>(wproj, out);
}

// round 7
// speedup vs baseline: 1.7587x; 1.7587x over previous
#include <cuda_runtime.h>
#include <cuda_bf16.h>
#include <mma.h>
#include <math.h>

using namespace nvcuda;

#define NB 2
#define NL 2048
#define NDM 1024
#define NH 16
#define NDH 64
#define NC 8
#define NPC 256
#define NG 16

typedef __nv_bfloat16 bf16;

// ---------------- scratch (device globals; no allocation allowed) -------------
__device__ float g_qkv[NB * NL * 3 * NDM];   // (B, L, 3, H, DH)
__device__ float g_qT[NB * NH * NL * NDH];   // (B, H, L, DH)
__device__ float g_kT[NB * NH * NL * NDH];
__device__ float g_vT[NB * NH * NL * NDH];
__device__ float g_oT[NB * NH * NL * NDH];
__device__ float g_oTok[NB * NL * NDM];      // (B, L, H*DH)
__device__ float g_P [NB * NC * 16];
__device__ float g_Pi[NB * NC * 16];
__device__ float g_Dt[NPC * NG * 4];         // (p, g) -> ca, sa, cb, sb

__device__ __forceinline__ void split_bf16(float x, bf16& h, bf16& l) {
    h = __float2bfloat16(x);
    l = __float2bfloat16(x - __bfloat162float(h));
}

// ---------------- per-camera P and P^{-1} -------------------------------------
__global__ void prope_mats(const float* __restrict__ vm, const float* __restrict__ Km) {
    int i = threadIdx.x;
    if (i >= NB * NC) return;
    const float* V = vm + i * 16;
    const float* Kc = Km + i * 9;
    double P[16];
    for (int r = 0; r < 3; r++)
        for (int j = 0; j < 4; j++) {
            double s = 0.0;
            for (int m = 0; m < 3; m++) s += (double)Kc[r * 3 + m] * (double)V[m * 4 + j];
            P[r * 4 + j] = s;
        }
    P[12] = V[12]; P[13] = V[13]; P[14] = V[14]; P[15] = V[15];
    for (int t = 0; t < 16; t++) g_P[i * 16 + t] = (float)P[t];

    double a00 = P[0], a01 = P[1], a02 = P[2];
    double a10 = P[4], a11 = P[5], a12 = P[6];
    double a20 = P[8], a21 = P[9], a22 = P[10];
    double c00 =  a11 * a22 - a12 * a21;
    double c01 = -(a10 * a22 - a12 * a20);
    double c02 =  a10 * a21 - a11 * a20;
    double det = a00 * c00 + a01 * c01 + a02 * c02;
    double id = 1.0 / det;
    double i00 = c00 * id;
    double i01 = (a02 * a21 - a01 * a22) * id;
    double i02 = (a01 * a12 - a02 * a11) * id;
    double i10 = c01 * id;
    double i11 = (a00 * a22 - a02 * a20) * id;
    double i12 = (a02 * a10 - a00 * a12) * id;
    double i20 = c02 * id;
    double i21 = (a01 * a20 - a00 * a21) * id;
    double i22 = (a00 * a11 - a01 * a10) * id;
    double b0 = P[3], b1 = P[7], b2 = P[11];
    double Pi[16] = { i00, i01, i02, -(i00 * b0 + i01 * b1 + i02 * b2),
                      i10, i11, i12, -(i10 * b0 + i11 * b1 + i12 * b2),
                      i20, i21, i22, -(i20 * b0 + i21 * b1 + i22 * b2),
                      0.0, 0.0, 0.0, 1.0 };
    for (int t = 0; t < 16; t++) g_Pi[i * 16 + t] = (float)Pi[t];
}

// ---------------- RoPE rotation table -----------------------------------------
__global__ void prope_dtab() {
    int idx = blockIdx.x * blockDim.x + threadIdx.x;
    if (idx >= NPC * NG) return;
    int p = idx >> 4, g = idx & 15;
    float u = ((p & 15) + 0.5f) * 16.0f;
    float v = ((p >> 4) + 0.5f) * 16.0f;
    float freq = (float)pow(10000.0, -(double)g / 16.0);
    float tu = u * freq;
    float tv = v * freq;
    g_Dt[idx * 4 + 0] = (float)cos((double)tu);
    g_Dt[idx * 4 + 1] = (float)sin((double)tu);
    g_Dt[idx * 4 + 2] = (float)cos((double)tv);
    g_Dt[idx * 4 + 3] = (float)sin((double)tv);
}

// ---------------- bf16x3 wmma GEMM: C[m][n] = sum_k A[m][k]*B[n][k] ------------
// Block tile 128x128, k-tile 32 (2 x k16). 8 warps: 2(m) x 4(n); warp tile 64x32.
#define GST 40   // bf16 smem stride: 32 k + 8 pad (80 bytes/row, 16B aligned)

__device__ __forceinline__ void gemm_bf16x3_body(const float* __restrict__ A,
                                                 const float* __restrict__ Bw,
                                                 float* __restrict__ C, int N, int K) {
    __shared__ bf16 As_h[128 * GST];
    __shared__ bf16 As_l[128 * GST];
    __shared__ bf16 Bs_h[128 * GST];
    __shared__ bf16 Bs_l[128 * GST];
    const int tid = threadIdx.x;
    const int wid = tid >> 5;
    const int wm = wid >> 2;            // 0..1
    const int wn = wid & 3;             // 0..3
    const int m0 = blockIdx.y * 128;
    const int n0 = blockIdx.x * 128;

    wmma::fragment<wmma::accumulator, 16, 16, 16, float> acc[4][2];
#pragma unroll
    for (int mi = 0; mi < 4; mi++)
#pragma unroll
        for (int ni = 0; ni < 2; ni++) wmma::fill_fragment(acc[mi][ni], 0.0f);

    for (int k0 = 0; k0 < K; k0 += 32) {
        __syncthreads();
#pragma unroll
        for (int i = tid; i < 1024; i += 256) {
            int rr = i >> 3, kc = (i & 7) << 2;
            float4 av = *(const float4*)(A  + (size_t)(m0 + rr) * K + k0 + kc);
            float4 bv = *(const float4*)(Bw + (size_t)(n0 + rr) * K + k0 + kc);
            bf16 h0, l0, h1, l1, h2, l2, h3, l3;
            split_bf16(av.x, h0, l0); split_bf16(av.y, h1, l1);
            split_bf16(av.z, h2, l2); split_bf16(av.w, h3, l3);
            As_h[rr * GST + kc] = h0; As_h[rr * GST + kc + 1] = h1;
            As_h[rr * GST + kc + 2] = h2; As_h[rr * GST + kc + 3] = h3;
            As_l[rr * GST + kc] = l0; As_l[rr * GST + kc + 1] = l1;
            As_l[rr * GST + kc + 2] = l2; As_l[rr * GST + kc + 3] = l3;
            split_bf16(bv.x, h0, l0); split_bf16(bv.y, h1, l1);
            split_bf16(bv.z, h2, l2); split_bf16(bv.w, h3, l3);
            Bs_h[rr * GST + kc] = h0; Bs_h[rr * GST + kc + 1] = h1;
            Bs_h[rr * GST + kc + 2] = h2; Bs_h[rr * GST + kc + 3] = h3;
            Bs_l[rr * GST + kc] = l0; Bs_l[rr * GST + kc + 1] = l1;
            Bs_l[rr * GST + kc + 2] = l2; Bs_l[rr * GST + kc + 3] = l3;
        }
        __syncthreads();
#pragma unroll
        for (int kk = 0; kk < 2; kk++) {
            wmma::fragment<wmma::matrix_a, 16, 16, 16, bf16, wmma::row_major> ah[4], al[4];
#pragma unroll
            for (int mi = 0; mi < 4; mi++) {
                wmma::load_matrix_sync(ah[mi], &As_h[(wm * 64 + mi * 16) * GST + kk * 16], GST);
                wmma::load_matrix_sync(al[mi], &As_l[(wm * 64 + mi * 16) * GST + kk * 16], GST);
            }
#pragma unroll
            for (int ni = 0; ni < 2; ni++) {
                wmma::fragment<wmma::matrix_b, 16, 16, 16, bf16, wmma::col_major> bh, bl;
                wmma::load_matrix_sync(bh, &Bs_h[(wn * 32 + ni * 16) * GST + kk * 16], GST);
                wmma::load_matrix_sync(bl, &Bs_l[(wn * 32 + ni * 16) * GST + kk * 16], GST);
#pragma unroll
                for (int mi = 0; mi < 4; mi++) {
                    wmma::mma_sync(acc[mi][ni], ah[mi], bl, acc[mi][ni]);
                    wmma::mma_sync(acc[mi][ni], al[mi], bh, acc[mi][ni]);
                    wmma::mma_sync(acc[mi][ni], ah[mi], bh, acc[mi][ni]);
                }
            }
        }
    }
#pragma unroll
    for (int mi = 0; mi < 4; mi++)
#pragma unroll
        for (int ni = 0; ni < 2; ni++)
            wmma::store_matrix_sync(C + (size_t)(m0 + wm * 64 + mi * 16) * N + n0 + wn * 32 + ni * 16,
                                    acc[mi][ni], N, wmma::mem_row_major);
}

__global__ void __launch_bounds__(256) k_gemm_qkv(const float* __restrict__ x,
                                                  const float* __restrict__ w) {
    gemm_bf16x3_body(x, w, g_qkv, 3 * NDM, NDM);
}
__global__ void __launch_bounds__(256) k_gemm_proj(const float* __restrict__ w,
                                                   float* __restrict__ out) {
    gemm_bf16x3_body(g_oTok, w, out, NDM, NDM);
}

// ---------------- apply Mq / Mkv to q, k, v ------------------------------------
__global__ void k_transform_qkv() {
    int idx = blockIdx.x * blockDim.x + threadIdx.x;
    if (idx >= NB * NH * NL * NG) return;
    int g = idx & 15;
    int l = (idx >> 4) & (NL - 1);
    int h = (idx >> 15) & 15;
    int b = idx >> 19;
    int c = l >> 8, p = l & 255;
    const float* Pm = g_P  + (b * NC + c) * 16;
    const float* Pi = g_Pi + (b * NC + c) * 16;
    float4 dv = *(const float4*)(g_Dt + (p * NG + g) * 4);
    float ca = dv.x, sa = dv.y, cb = dv.z, sb = dv.w;

    size_t base = ((size_t)(b * NL + l) * 3) * NDM + h * NDH + g * 4;
    size_t obase = ((size_t)(b * NH + h) * NL + l) * NDH + g * 4;

    {
        float4 t = *(const float4*)(g_qkv + base);
        float d0 = ca * t.x - sa * t.y, d1 = sa * t.x + ca * t.y;
        float d2 = cb * t.z - sb * t.w, d3 = sb * t.z + cb * t.w;
        float4 o;
        o.x = Pi[0] * d0 + Pi[4] * d1 + Pi[8]  * d2 + Pi[12] * d3;
        o.y = Pi[1] * d0 + Pi[5] * d1 + Pi[9]  * d2 + Pi[13] * d3;
        o.z = Pi[2] * d0 + Pi[6] * d1 + Pi[10] * d2 + Pi[14] * d3;
        o.w = Pi[3] * d0 + Pi[7] * d1 + Pi[11] * d2 + Pi[15] * d3;
        *(float4*)(g_qT + obase) = o;
    }
    {
        float4 t = *(const float4*)(g_qkv + base + NDM);
        float d0 = ca * t.x - sa * t.y, d1 = sa * t.x + ca * t.y;
        float d2 = cb * t.z - sb * t.w, d3 = sb * t.z + cb * t.w;
        float4 o;
        o.x = Pm[0]  * d0 + Pm[1]  * d1 + Pm[2]  * d2 + Pm[3]  * d3;
        o.y = Pm[4]  * d0 + Pm[5]  * d1 + Pm[6]  * d2 + Pm[7]  * d3;
        o.z = Pm[8]  * d0 + Pm[9]  * d1 + Pm[10] * d2 + Pm[11] * d3;
        o.w = Pm[12] * d0 + Pm[13] * d1 + Pm[14] * d2 + Pm[15] * d3;
        *(float4*)(g_kT + obase) = o;
    }
    {
        float4 t = *(const float4*)(g_qkv + base + 2 * NDM);
        float d0 = ca * t.x - sa * t.y, d1 = sa * t.x + ca * t.y;
        float d2 = cb * t.z - sb * t.w, d3 = sb * t.z + cb * t.w;
        float4 o;
        o.x = Pm[0]  * d0 + Pm[1]  * d1 + Pm[2]  * d2 + Pm[3]  * d3;
        o.y = Pm[4]  * d0 + Pm[5]  * d1 + Pm[6]  * d2 + Pm[7]  * d3;
        o.z = Pm[8]  * d0 + Pm[9]  * d1 + Pm[10] * d2 + Pm[11] * d3;
        o.w = Pm[12] * d0 + Pm[13] * d1 + Pm[14] * d2 + Pm[15] * d3;
        *(float4*)(g_vT + obase) = o;
    }
}

// ---------------- flash attention (bf16x3 wmma, BM=64 q rows, BN=64 kv) --------
// 8 warps: warp w -> row-group rg = w>>1 (16 q rows), half = w&1 (32-col half).
// bf16 tiles stride 72 (144 B/row, 16B aligned, mult of 8 elems).
#define FST 72
#define FL_T  (64 * FST)          // elements per 64-row tile

#define OFF_KH 0
#define OFF_KL (OFF_KH + FL_T)
#define OFF_VH (OFF_KL + FL_T)
#define OFF_VL (OFF_VH + FL_T)
#define OFF_QH (OFF_VL + FL_T)    // reused as P_hi after Q fragments loaded
#define OFF_QL (OFF_QH + FL_T)    // reused as P_lo
#define BF_ELEMS (OFF_QL + FL_T)

#define FLASH_SMEM (BF_ELEMS * 2 + (2 * FL_T + 128) * 4)

__global__ void __launch_bounds__(256) k_flash() {
    extern __shared__ char fshraw[];
    bf16*  bfb  = (bf16*)fshraw;
    float* Ss   = (float*)(fshraw + BF_ELEMS * 2);
    float* Os   = Ss + FL_T;
    float* m_sm = Os + FL_T;
    float* l_sm = m_sm + 64;

    bf16* Ks_h = bfb + OFF_KH; bf16* Ks_l = bfb + OFF_KL;
    bf16* Vs_h = bfb + OFF_VH; bf16* Vs_l = bfb + OFF_VL;
    bf16* Qs_h = bfb + OFF_QH; bf16* Qs_l = bfb + OFF_QL;
    bf16* Ps_h = Qs_h;         bf16* Ps_l = Qs_l;

    const int tid = threadIdx.x;
    const int lane = tid & 31;
    const int w = tid >> 5;
    const int rg = w >> 1;           // 0..3: q rows rg*16..+16
    const int half = w & 1;          // 0..1: 32-col half

    const int bh = blockIdx.y;
    const int q0 = blockIdx.x * 64;

    const float* Qg = g_qT + (size_t)bh * NL * NDH;
    const float* Kg = g_kT + (size_t)bh * NL * NDH;
    const float* Vg = g_vT + (size_t)bh * NL * NDH;
    float* Og       = g_oT + (size_t)bh * NL * NDH;

    // init O, m, l; stage Q split
    for (int i = tid; i < FL_T; i += 256) Os[i] = 0.f;
    if (tid < 64) { m_sm[tid] = -1e30f; l_sm[tid] = 0.f; }
    for (int i = tid; i < 64 * 16; i += 256) {
        int rr = i >> 4, cc = (i & 15) << 2;
        float4 t = *(const float4*)(Qg + (size_t)(q0 + rr) * NDH + cc);
        bf16 h, l;
        split_bf16(t.x, h, l); Qs_h[rr * FST + cc]     = h; Qs_l[rr * FST + cc]     = l;
        split_bf16(t.y, h, l); Qs_h[rr * FST + cc + 1] = h; Qs_l[rr * FST + cc + 1] = l;
        split_bf16(t.z, h, l); Qs_h[rr * FST + cc + 2] = h; Qs_l[rr * FST + cc + 2] = l;
        split_bf16(t.w, h, l); Qs_h[rr * FST + cc + 3] = h; Qs_l[rr * FST + cc + 3] = l;
    }
    __syncthreads();

    // preload Q fragments (4 k-steps over d=64)
    wmma::fragment<wmma::matrix_a, 16, 16, 16, bf16, wmma::row_major> aqh[4], aql[4];
#pragma unroll
    for (int kk = 0; kk < 4; kk++) {
        wmma::load_matrix_sync(aqh[kk], &Qs_h[(rg * 16) * FST + kk * 16], FST);
        wmma::load_matrix_sync(aql[kk], &Qs_l[(rg * 16) * FST + kk * 16], FST);
    }
    __syncthreads();   // everyone has fragments; Qs can be reused as Ps

    for (int n0 = 0; n0 < NL; n0 += 64) {
        // load + split K/V tile 64x64
        for (int i = tid; i < 64 * 16; i += 256) {
            int rr = i >> 4, cc = (i & 15) << 2;
            float4 kt = *(const float4*)(Kg + (size_t)(n0 + rr) * NDH + cc);
            float4 vt = *(const float4*)(Vg + (size_t)(n0 + rr) * NDH + cc);
            bf16 h, l;
            split_bf16(kt.x, h, l); Ks_h[rr * FST + cc]     = h; Ks_l[rr * FST + cc]     = l;
            split_bf16(kt.y, h, l); Ks_h[rr * FST + cc + 1] = h; Ks_l[rr * FST + cc + 1] = l;
            split_bf16(kt.z, h, l); Ks_h[rr * FST + cc + 2] = h; Ks_l[rr * FST + cc + 2] = l;
            split_bf16(kt.w, h, l); Ks_h[rr * FST + cc + 3] = h; Ks_l[rr * FST + cc + 3] = l;
            split_bf16(vt.x, h, l); Vs_h[rr * FST + cc]     = h; Vs_l[rr * FST + cc]     = l;
            split_bf16(vt.y, h, l); Vs_h[rr * FST + cc + 1] = h; Vs_l[rr * FST + cc + 1] = l;
            split_bf16(vt.z, h, l); Vs_h[rr * FST + cc + 2] = h; Vs_l[rr * FST + cc + 2] = l;
            split_bf16(vt.w, h, l); Vs_h[rr * FST + cc + 3] = h; Vs_l[rr * FST + cc + 3] = l;
        }
        __syncthreads();

        // S = Q K^T : warp covers rows rg*16..+16, kv cols half*32..+32
        wmma::fragment<wmma::accumulator, 16, 16, 16, float> sfrag[2];
#pragma unroll
        for (int nt = 0; nt < 2; nt++) wmma::fill_fragment(sfrag[nt], 0.f);
#pragma unroll
        for (int kk = 0; kk < 4; kk++) {
#pragma unroll
            for (int nt = 0; nt < 2; nt++) {
                wmma::fragment<wmma::matrix_b, 16, 16, 16, bf16, wmma::col_major> bh, bl;
                int kvrow = half * 32 + nt * 16;
                wmma::load_matrix_sync(bh, &Ks_h[kvrow * FST + kk * 16], FST);
                wmma::load_matrix_sync(bl, &Ks_l[kvrow * FST + kk * 16], FST);
                wmma::mma_sync(sfrag[nt], aqh[kk], bl, sfrag[nt]);
                wmma::mma_sync(sfrag[nt], aql[kk], bh, sfrag[nt]);
                wmma::mma_sync(sfrag[nt], aqh[kk], bh, sfrag[nt]);
            }
        }
#pragma unroll
        for (int nt = 0; nt < 2; nt++)
            wmma::store_matrix_sync(&Ss[(rg * 16) * FST + half * 32 + nt * 16],
                                    sfrag[nt], FST, wmma::mem_row_major);
        __syncthreads();

        // online softmax: 4 threads per row, 16 cols each
        {
            int r = tid >> 2;            // 0..63
            int qd = tid & 3;
            float* srow = &Ss[r * FST + qd * 16];
            float sv[16];
            float mloc = -1e30f;
#pragma unroll
            for (int j = 0; j < 16; j++) {
                sv[j] = srow[j] * 0.125f;
                mloc = fmaxf(mloc, sv[j]);
            }
            mloc = fmaxf(mloc, __shfl_xor_sync(0xffffffffu, mloc, 1));
            mloc = fmaxf(mloc, __shfl_xor_sync(0xffffffffu, mloc, 2));
            float m_old = m_sm[r];
            float m_new = fmaxf(m_old, mloc);
            float alpha = __expf(m_old - m_new);
            float lsum = 0.f;
            bf16* ph = &Ps_h[r * FST + qd * 16];
            bf16* pl = &Ps_l[r * FST + qd * 16];
#pragma unroll
            for (int j = 0; j < 16; j++) {
                float p = __expf(sv[j] - m_new);
                lsum += p;
                bf16 h, l;
                split_bf16(p, h, l);
                ph[j] = h; pl[j] = l;
            }
            lsum += __shfl_xor_sync(0xffffffffu, lsum, 1);
            lsum += __shfl_xor_sync(0xffffffffu, lsum, 2);
            if (qd == 0) {
                m_sm[r] = m_new;
                l_sm[r] = l_sm[r] * alpha + lsum;
            }
            // rescale O row segment
            float* orow = &Os[r * FST + qd * 16];
#pragma unroll
            for (int j = 0; j < 16; j++) orow[j] *= alpha;
        }
        __syncthreads();

        // O += P V : warp covers rows rg*16..+16, d cols half*32..+32
        wmma::fragment<wmma::accumulator, 16, 16, 16, float> ofrag[2];
#pragma unroll
        for (int nt = 0; nt < 2; nt++)
            wmma::load_matrix_sync(ofrag[nt], &Os[(rg * 16) * FST + half * 32 + nt * 16],
                                   FST, wmma::mem_row_major);
#pragma unroll
        for (int kk = 0; kk < 4; kk++) {
            wmma::fragment<wmma::matrix_a, 16, 16, 16, bf16, wmma::row_major> aph, apl;
            wmma::load_matrix_sync(aph, &Ps_h[(rg * 16) * FST + kk * 16], FST);
            wmma::load_matrix_sync(apl, &Ps_l[(rg * 16) * FST + kk * 16], FST);
#pragma unroll
            for (int nt = 0; nt < 2; nt++) {
                wmma::fragment<wmma::matrix_b, 16, 16, 16, bf16, wmma::row_major> vh, vl;
                int dcol = half * 32 + nt * 16;
                wmma::load_matrix_sync(vh, &Vs_h[(kk * 16) * FST + dcol], FST);
                wmma::load_matrix_sync(vl, &Vs_l[(kk * 16) * FST + dcol], FST);
                wmma::mma_sync(ofrag[nt], aph, vl, ofrag[nt]);
                wmma::mma_sync(ofrag[nt], apl, vh, ofrag[nt]);
                wmma::mma_sync(ofrag[nt], aph, vh, ofrag[nt]);
            }
        }
#pragma unroll
        for (int nt = 0; nt < 2; nt++)
            wmma::store_matrix_sync(&Os[(rg * 16) * FST + half * 32 + nt * 16],
                                    ofrag[nt], FST, wmma::mem_row_major);
        __syncthreads();
    }

    // normalize and write out
    for (int i = tid; i < 64 * 16; i += 256) {
        int rr = i >> 4, cc = (i & 15) << 2;
        float inv = 1.f / l_sm[rr];
        float4 ov = *(float4*)&Os[rr * FST + cc];
        ov.x *= inv; ov.y *= inv; ov.z *= inv; ov.w *= inv;
        *(float4*)(Og + (size_t)(q0 + rr) * NDH + cc) = ov;
    }
}

// ---------------- apply Mo to o, write token-major -----------------------------
__global__ void k_transform_o() {
    int idx = blockIdx.x * blockDim.x + threadIdx.x;
    if (idx >= NB * NH * NL * NG) return;
    int g = idx & 15;
    int l = (idx >> 4) & (NL - 1);
    int h = (idx >> 15) & 15;
    int b = idx >> 19;
    int c = l >> 8, p = l & 255;
    const float* Pi = g_Pi + (b * NC + c) * 16;
    float4 dv = *(const float4*)(g_Dt + (p * NG + g) * 4);
    float ca = dv.x, sa = dv.y, cb = dv.z, sb = dv.w;

    float4 t = *(const float4*)(g_oT + ((size_t)(b * NH + h) * NL + l) * NDH + g * 4);
    float z0 = Pi[0]  * t.x + Pi[1]  * t.y + Pi[2]  * t.z + Pi[3]  * t.w;
    float z1 = Pi[4]  * t.x + Pi[5]  * t.y + Pi[6]  * t.z + Pi[7]  * t.w;
    float z2 = Pi[8]  * t.x + Pi[9]  * t.y + Pi[10] * t.z + Pi[11] * t.w;
    float z3 = Pi[12] * t.x + Pi[13] * t.y + Pi[14] * t.z + Pi[15] * t.w;
    float4 o;
    o.x =  ca * z0 + sa * z1;
    o.y = -sa * z0 + ca * z1;
    o.z =  cb * z2 + sb * z3;
    o.w = -sb * z2 + cb * z3;
    *(float4*)(g_oTok + (size_t)(b * NL + l) * NDM + h * NDH + g * 4) = o;
}

// ---------------- launch --------------------------------------------------------
extern "C" void kernel_launch(void* const* d_in, const int* in_sizes, int n_in,
                              void* d_out, int out_size) {
    (void)in_sizes; (void)n_in; (void)out_size;
    const float* x     = (const float*)d_in[0];
    const float* vm    = (const float*)d_in[1];
    const float* Km    = (const float*)d_in[2];
    const float* wqkv  = (const float*)d_in[3];
    const float* wproj = (const float*)d_in[4];
    float* out = (float*)d_out;

    cudaFuncSetAttribute(k_flash, cudaFuncAttributeMaxDynamicSharedMemorySize, FLASH_SMEM);

    prope_mats<<<1, 32>>>(vm, Km);
    prope_dtab<<<16, 256>>>();
    k_gemm_qkv<<<dim3(3 * NDM / 128, NB * NL / 128), 256>>>(x, wqkv);
    k_transform_qkv<<<(NB * NH * NL * NG) / 256, 256>>>();
    k_flash<<<dim3(NL / 64, NB * NH), 256, FLASH_SMEM>>>();
    k_transform_o<<<(NB * NH * NL * NG) / 256, 256>>>();
    k_gemm_proj<<<dim3(NDM / 128, NB * NL / 128), 256>>>(wproj, out);
}

// round 8
// speedup vs baseline: 1.7702x; 1.0065x over previous
#include <cuda_runtime.h>
#include <cuda_bf16.h>
#include <mma.h>
#include <math.h>

using namespace nvcuda;

#define NB 2
#define NL 2048
#define NDM 1024
#define NH 16
#define NDH 64
#define NC 8
#define NPC 256
#define NG 16

typedef __nv_bfloat16 bf16;

// ---------------- scratch (device globals; no allocation allowed) -------------
__device__ float g_qkv[NB * NL * 3 * NDM];   // (B, L, 3, H, DH)
__device__ float g_qT[NB * NH * NL * NDH];   // (B, H, L, DH)
__device__ float g_kT[NB * NH * NL * NDH];
__device__ float g_vT[NB * NH * NL * NDH];
__device__ float g_oT[NB * NH * NL * NDH];
__device__ float g_oTok[NB * NL * NDM];      // (B, L, H*DH)
__device__ float g_P [NB * NC * 16];
__device__ float g_Pi[NB * NC * 16];
__device__ float g_Dt[NPC * NG * 4];         // (p, g) -> ca, sa, cb, sb

__device__ __forceinline__ void split_bf16(float x, bf16& h, bf16& l) {
    h = __float2bfloat16(x);
    l = __float2bfloat16(x - __bfloat162float(h));
}

// ---------------- per-camera P and P^{-1} -------------------------------------
__global__ void prope_mats(const float* __restrict__ vm, const float* __restrict__ Km) {
    int i = threadIdx.x;
    if (i >= NB * NC) return;
    const float* V = vm + i * 16;
    const float* Kc = Km + i * 9;
    double P[16];
    for (int r = 0; r < 3; r++)
        for (int j = 0; j < 4; j++) {
            double s = 0.0;
            for (int m = 0; m < 3; m++) s += (double)Kc[r * 3 + m] * (double)V[m * 4 + j];
            P[r * 4 + j] = s;
        }
    P[12] = V[12]; P[13] = V[13]; P[14] = V[14]; P[15] = V[15];
    for (int t = 0; t < 16; t++) g_P[i * 16 + t] = (float)P[t];

    double a00 = P[0], a01 = P[1], a02 = P[2];
    double a10 = P[4], a11 = P[5], a12 = P[6];
    double a20 = P[8], a21 = P[9], a22 = P[10];
    double c00 =  a11 * a22 - a12 * a21;
    double c01 = -(a10 * a22 - a12 * a20);
    double c02 =  a10 * a21 - a11 * a20;
    double det = a00 * c00 + a01 * c01 + a02 * c02;
    double id = 1.0 / det;
    double i00 = c00 * id;
    double i01 = (a02 * a21 - a01 * a22) * id;
    double i02 = (a01 * a12 - a02 * a11) * id;
    double i10 = c01 * id;
    double i11 = (a00 * a22 - a02 * a20) * id;
    double i12 = (a02 * a10 - a00 * a12) * id;
    double i20 = c02 * id;
    double i21 = (a01 * a20 - a00 * a21) * id;
    double i22 = (a00 * a11 - a01 * a10) * id;
    double b0 = P[3], b1 = P[7], b2 = P[11];
    double Pi[16] = { i00, i01, i02, -(i00 * b0 + i01 * b1 + i02 * b2),
                      i10, i11, i12, -(i10 * b0 + i11 * b1 + i12 * b2),
                      i20, i21, i22, -(i20 * b0 + i21 * b1 + i22 * b2),
                      0.0, 0.0, 0.0, 1.0 };
    for (int t = 0; t < 16; t++) g_Pi[i * 16 + t] = (float)Pi[t];
}

// ---------------- RoPE rotation table -----------------------------------------
__global__ void prope_dtab() {
    int idx = blockIdx.x * blockDim.x + threadIdx.x;
    if (idx >= NPC * NG) return;
    int p = idx >> 4, g = idx & 15;
    float u = ((p & 15) + 0.5f) * 16.0f;
    float v = ((p >> 4) + 0.5f) * 16.0f;
    float freq = (float)pow(10000.0, -(double)g / 16.0);
    float tu = u * freq;
    float tv = v * freq;
    g_Dt[idx * 4 + 0] = (float)cos((double)tu);
    g_Dt[idx * 4 + 1] = (float)sin((double)tu);
    g_Dt[idx * 4 + 2] = (float)cos((double)tv);
    g_Dt[idx * 4 + 3] = (float)sin((double)tv);
}

// ---------------- bf16x3 wmma GEMM: C[m][n] = sum_k A[m][k]*B[n][k] ------------
// Block tile 128x128, k-tile 32 (2 x k16). 8 warps: 2(m) x 4(n); warp tile 64x32.
#define GST 40   // bf16 smem stride: 32 k + 8 pad (80 bytes/row, 16B aligned)

__device__ __forceinline__ void gemm_bf16x3_body(const float* __restrict__ A,
                                                 const float* __restrict__ Bw,
                                                 float* __restrict__ C, int N, int K) {
    __shared__ bf16 As_h[128 * GST];
    __shared__ bf16 As_l[128 * GST];
    __shared__ bf16 Bs_h[128 * GST];
    __shared__ bf16 Bs_l[128 * GST];
    const int tid = threadIdx.x;
    const int wid = tid >> 5;
    const int wm = wid >> 2;            // 0..1
    const int wn = wid & 3;             // 0..3
    const int m0 = blockIdx.y * 128;
    const int n0 = blockIdx.x * 128;

    wmma::fragment<wmma::accumulator, 16, 16, 16, float> acc[4][2];
#pragma unroll
    for (int mi = 0; mi < 4; mi++)
#pragma unroll
        for (int ni = 0; ni < 2; ni++) wmma::fill_fragment(acc[mi][ni], 0.0f);

    for (int k0 = 0; k0 < K; k0 += 32) {
        __syncthreads();
#pragma unroll
        for (int i = tid; i < 1024; i += 256) {
            int rr = i >> 3, kc = (i & 7) << 2;
            float4 av = *(const float4*)(A  + (size_t)(m0 + rr) * K + k0 + kc);
            float4 bv = *(const float4*)(Bw + (size_t)(n0 + rr) * K + k0 + kc);
            bf16 h0, l0, h1, l1, h2, l2, h3, l3;
            split_bf16(av.x, h0, l0); split_bf16(av.y, h1, l1);
            split_bf16(av.z, h2, l2); split_bf16(av.w, h3, l3);
            As_h[rr * GST + kc] = h0; As_h[rr * GST + kc + 1] = h1;
            As_h[rr * GST + kc + 2] = h2; As_h[rr * GST + kc + 3] = h3;
            As_l[rr * GST + kc] = l0; As_l[rr * GST + kc + 1] = l1;
            As_l[rr * GST + kc + 2] = l2; As_l[rr * GST + kc + 3] = l3;
            split_bf16(bv.x, h0, l0); split_bf16(bv.y, h1, l1);
            split_bf16(bv.z, h2, l2); split_bf16(bv.w, h3, l3);
            Bs_h[rr * GST + kc] = h0; Bs_h[rr * GST + kc + 1] = h1;
            Bs_h[rr * GST + kc + 2] = h2; Bs_h[rr * GST + kc + 3] = h3;
            Bs_l[rr * GST + kc] = l0; Bs_l[rr * GST + kc + 1] = l1;
            Bs_l[rr * GST + kc + 2] = l2; Bs_l[rr * GST + kc + 3] = l3;
        }
        __syncthreads();
#pragma unroll
        for (int kk = 0; kk < 2; kk++) {
            wmma::fragment<wmma::matrix_a, 16, 16, 16, bf16, wmma::row_major> ah[4], al[4];
#pragma unroll
            for (int mi = 0; mi < 4; mi++) {
                wmma::load_matrix_sync(ah[mi], &As_h[(wm * 64 + mi * 16) * GST + kk * 16], GST);
                wmma::load_matrix_sync(al[mi], &As_l[(wm * 64 + mi * 16) * GST + kk * 16], GST);
            }
#pragma unroll
            for (int ni = 0; ni < 2; ni++) {
                wmma::fragment<wmma::matrix_b, 16, 16, 16, bf16, wmma::col_major> bh, bl;
                wmma::load_matrix_sync(bh, &Bs_h[(wn * 32 + ni * 16) * GST + kk * 16], GST);
                wmma::load_matrix_sync(bl, &Bs_l[(wn * 32 + ni * 16) * GST + kk * 16], GST);
#pragma unroll
                for (int mi = 0; mi < 4; mi++) {
                    wmma::mma_sync(acc[mi][ni], ah[mi], bl, acc[mi][ni]);
                    wmma::mma_sync(acc[mi][ni], al[mi], bh, acc[mi][ni]);
                    wmma::mma_sync(acc[mi][ni], ah[mi], bh, acc[mi][ni]);
                }
            }
        }
    }
#pragma unroll
    for (int mi = 0; mi < 4; mi++)
#pragma unroll
        for (int ni = 0; ni < 2; ni++)
            wmma::store_matrix_sync(C + (size_t)(m0 + wm * 64 + mi * 16) * N + n0 + wn * 32 + ni * 16,
                                    acc[mi][ni], N, wmma::mem_row_major);
}

__global__ void __launch_bounds__(256) k_gemm_qkv(const float* __restrict__ x,
                                                  const float* __restrict__ w) {
    gemm_bf16x3_body(x, w, g_qkv, 3 * NDM, NDM);
}
__global__ void __launch_bounds__(256) k_gemm_proj(const float* __restrict__ w,
                                                   float* __restrict__ out) {
    gemm_bf16x3_body(g_oTok, w, out, NDM, NDM);
}

// ---------------- apply Mq / Mkv to q, k, v ------------------------------------
__global__ void k_transform_qkv() {
    int idx = blockIdx.x * blockDim.x + threadIdx.x;
    if (idx >= NB * NH * NL * NG) return;
    int g = idx & 15;
    int l = (idx >> 4) & (NL - 1);
    int h = (idx >> 15) & 15;
    int b = idx >> 19;
    int c = l >> 8, p = l & 255;
    const float* Pm = g_P  + (b * NC + c) * 16;
    const float* Pi = g_Pi + (b * NC + c) * 16;
    float4 dv = *(const float4*)(g_Dt + (p * NG + g) * 4);
    float ca = dv.x, sa = dv.y, cb = dv.z, sb = dv.w;

    size_t base = ((size_t)(b * NL + l) * 3) * NDM + h * NDH + g * 4;
    size_t obase = ((size_t)(b * NH + h) * NL + l) * NDH + g * 4;

    {
        float4 t = *(const float4*)(g_qkv + base);
        float d0 = ca * t.x - sa * t.y, d1 = sa * t.x + ca * t.y;
        float d2 = cb * t.z - sb * t.w, d3 = sb * t.z + cb * t.w;
        float4 o;
        o.x = Pi[0] * d0 + Pi[4] * d1 + Pi[8]  * d2 + Pi[12] * d3;
        o.y = Pi[1] * d0 + Pi[5] * d1 + Pi[9]  * d2 + Pi[13] * d3;
        o.z = Pi[2] * d0 + Pi[6] * d1 + Pi[10] * d2 + Pi[14] * d3;
        o.w = Pi[3] * d0 + Pi[7] * d1 + Pi[11] * d2 + Pi[15] * d3;
        *(float4*)(g_qT + obase) = o;
    }
    {
        float4 t = *(const float4*)(g_qkv + base + NDM);
        float d0 = ca * t.x - sa * t.y, d1 = sa * t.x + ca * t.y;
        float d2 = cb * t.z - sb * t.w, d3 = sb * t.z + cb * t.w;
        float4 o;
        o.x = Pm[0]  * d0 + Pm[1]  * d1 + Pm[2]  * d2 + Pm[3]  * d3;
        o.y = Pm[4]  * d0 + Pm[5]  * d1 + Pm[6]  * d2 + Pm[7]  * d3;
        o.z = Pm[8]  * d0 + Pm[9]  * d1 + Pm[10] * d2 + Pm[11] * d3;
        o.w = Pm[12] * d0 + Pm[13] * d1 + Pm[14] * d2 + Pm[15] * d3;
        *(float4*)(g_kT + obase) = o;
    }
    {
        float4 t = *(const float4*)(g_qkv + base + 2 * NDM);
        float d0 = ca * t.x - sa * t.y, d1 = sa * t.x + ca * t.y;
        float d2 = cb * t.z - sb * t.w, d3 = sb * t.z + cb * t.w;
        float4 o;
        o.x = Pm[0]  * d0 + Pm[1]  * d1 + Pm[2]  * d2 + Pm[3]  * d3;
        o.y = Pm[4]  * d0 + Pm[5]  * d1 + Pm[6]  * d2 + Pm[7]  * d3;
        o.z = Pm[8]  * d0 + Pm[9]  * d1 + Pm[10] * d2 + Pm[11] * d3;
        o.w = Pm[12] * d0 + Pm[13] * d1 + Pm[14] * d2 + Pm[15] * d3;
        *(float4*)(g_vT + obase) = o;
    }
}

// ---------------- flash attention (bf16x3 wmma, BM=64 q rows, BN=64 kv) --------
// 8 warps: warp w -> row-group rg = w>>1 (16 q rows), half = w&1 (32-col half).
// bf16 tiles stride 72 (144 B/row, 16B aligned, mult of 8 elems).
#define FST 72
#define FL_T  (64 * FST)          // elements per 64-row tile

#define OFF_KH 0
#define OFF_KL (OFF_KH + FL_T)
#define OFF_VH (OFF_KL + FL_T)
#define OFF_VL (OFF_VH + FL_T)
#define OFF_QH (OFF_VL + FL_T)    // reused as P_hi after Q fragments loaded
#define OFF_QL (OFF_QH + FL_T)    // reused as P_lo
#define BF_ELEMS (OFF_QL + FL_T)

#define FLASH_SMEM (BF_ELEMS * 2 + (2 * FL_T + 128) * 4)

__global__ void __launch_bounds__(256) k_flash() {
    extern __shared__ char fshraw[];
    bf16*  bfb  = (bf16*)fshraw;
    float* Ss   = (float*)(fshraw + BF_ELEMS * 2);
    float* Os   = Ss + FL_T;
    float* m_sm = Os + FL_T;
    float* l_sm = m_sm + 64;

    bf16* Ks_h = bfb + OFF_KH; bf16* Ks_l = bfb + OFF_KL;
    bf16* Vs_h = bfb + OFF_VH; bf16* Vs_l = bfb + OFF_VL;
    bf16* Qs_h = bfb + OFF_QH; bf16* Qs_l = bfb + OFF_QL;
    bf16* Ps_h = Qs_h;         bf16* Ps_l = Qs_l;

    const int tid = threadIdx.x;
    const int lane = tid & 31;
    const int w = tid >> 5;
    const int rg = w >> 1;           // 0..3: q rows rg*16..+16
    const int half = w & 1;          // 0..1: 32-col half

    const int bh = blockIdx.y;
    const int q0 = blockIdx.x * 64;

    const float* Qg = g_qT + (size_t)bh * NL * NDH;
    const float* Kg = g_kT + (size_t)bh * NL * NDH;
    const float* Vg = g_vT + (size_t)bh * NL * NDH;
    float* Og       = g_oT + (size_t)bh * NL * NDH;

    // init O, m, l; stage Q split
    for (int i = tid; i < FL_T; i += 256) Os[i] = 0.f;
    if (tid < 64) { m_sm[tid] = -1e30f; l_sm[tid] = 0.f; }
    for (int i = tid; i < 64 * 16; i += 256) {
        int rr = i >> 4, cc = (i & 15) << 2;
        float4 t = *(const float4*)(Qg + (size_t)(q0 + rr) * NDH + cc);
        bf16 h, l;
        split_bf16(t.x, h, l); Qs_h[rr * FST + cc]     = h; Qs_l[rr * FST + cc]     = l;
        split_bf16(t.y, h, l); Qs_h[rr * FST + cc + 1] = h; Qs_l[rr * FST + cc + 1] = l;
        split_bf16(t.z, h, l); Qs_h[rr * FST + cc + 2] = h; Qs_l[rr * FST + cc + 2] = l;
        split_bf16(t.w, h, l); Qs_h[rr * FST + cc + 3] = h; Qs_l[rr * FST + cc + 3] = l;
    }
    __syncthreads();

    // preload Q fragments (4 k-steps over d=64)
    wmma::fragment<wmma::matrix_a, 16, 16, 16, bf16, wmma::row_major> aqh[4], aql[4];
#pragma unroll
    for (int kk = 0; kk < 4; kk++) {
        wmma::load_matrix_sync(aqh[kk], &Qs_h[(rg * 16) * FST + kk * 16], FST);
        wmma::load_matrix_sync(aql[kk], &Qs_l[(rg * 16) * FST + kk * 16], FST);
    }
    __syncthreads();   // everyone has fragments; Qs can be reused as Ps

    for (int n0 = 0; n0 < NL; n0 += 64) {
        // load + split K/V tile 64x64
        for (int i = tid; i < 64 * 16; i += 256) {
            int rr = i >> 4, cc = (i & 15) << 2;
            float4 kt = *(const float4*)(Kg + (size_t)(n0 + rr) * NDH + cc);
            float4 vt = *(const float4*)(Vg + (size_t)(n0 + rr) * NDH + cc);
            bf16 h, l;
            split_bf16(kt.x, h, l); Ks_h[rr * FST + cc]     = h; Ks_l[rr * FST + cc]     = l;
            split_bf16(kt.y, h, l); Ks_h[rr * FST + cc + 1] = h; Ks_l[rr * FST + cc + 1] = l;
            split_bf16(kt.z, h, l); Ks_h[rr * FST + cc + 2] = h; Ks_l[rr * FST + cc + 2] = l;
            split_bf16(kt.w, h, l); Ks_h[rr * FST + cc + 3] = h; Ks_l[rr * FST + cc + 3] = l;
            split_bf16(vt.x, h, l); Vs_h[rr * FST + cc]     = h; Vs_l[rr * FST + cc]     = l;
            split_bf16(vt.y, h, l); Vs_h[rr * FST + cc + 1] = h; Vs_l[rr * FST + cc + 1] = l;
            split_bf16(vt.z, h, l); Vs_h[rr * FST + cc + 2] = h; Vs_l[rr * FST + cc + 2] = l;
            split_bf16(vt.w, h, l); Vs_h[rr * FST + cc + 3] = h; Vs_l[rr * FST + cc + 3] = l;
        }
        __syncthreads();

        // S = Q K^T : warp covers rows rg*16..+16, kv cols half*32..+32
        wmma::fragment<wmma::accumulator, 16, 16, 16, float> sfrag[2];
#pragma unroll
        for (int nt = 0; nt < 2; nt++) wmma::fill_fragment(sfrag[nt], 0.f);
#pragma unroll
        for (int kk = 0; kk < 4; kk++) {
#pragma unroll
            for (int nt = 0; nt < 2; nt++) {
                wmma::fragment<wmma::matrix_b, 16, 16, 16, bf16, wmma::col_major> bh, bl;
                int kvrow = half * 32 + nt * 16;
                wmma::load_matrix_sync(bh, &Ks_h[kvrow * FST + kk * 16], FST);
                wmma::load_matrix_sync(bl, &Ks_l[kvrow * FST + kk * 16], FST);
                wmma::mma_sync(sfrag[nt], aqh[kk], bl, sfrag[nt]);
                wmma::mma_sync(sfrag[nt], aql[kk], bh, sfrag[nt]);
                wmma::mma_sync(sfrag[nt], aqh[kk], bh, sfrag[nt]);
            }
        }
#pragma unroll
        for (int nt = 0; nt < 2; nt++)
            wmma::store_matrix_sync(&Ss[(rg * 16) * FST + half * 32 + nt * 16],
                                    sfrag[nt], FST, wmma::mem_row_major);
        __syncthreads();

        // online softmax: 4 threads per row, 16 cols each
        {
            int r = tid >> 2;            // 0..63
            int qd = tid & 3;
            float* srow = &Ss[r * FST + qd * 16];
            float sv[16];
            float mloc = -1e30f;
#pragma unroll
            for (int j = 0; j < 16; j++) {
                sv[j] = srow[j] * 0.125f;
                mloc = fmaxf(mloc, sv[j]);
            }
            mloc = fmaxf(mloc, __shfl_xor_sync(0xffffffffu, mloc, 1));
            mloc = fmaxf(mloc, __shfl_xor_sync(0xffffffffu, mloc, 2));
            float m_old = m_sm[r];
            float m_new = fmaxf(m_old, mloc);
            float alpha = __expf(m_old - m_new);
            float lsum = 0.f;
            bf16* ph = &Ps_h[r * FST + qd * 16];
            bf16* pl = &Ps_l[r * FST + qd * 16];
#pragma unroll
            for (int j = 0; j < 16; j++) {
                float p = __expf(sv[j] - m_new);
                lsum += p;
                bf16 h, l;
                split_bf16(p, h, l);
                ph[j] = h; pl[j] = l;
            }
            lsum += __shfl_xor_sync(0xffffffffu, lsum, 1);
            lsum += __shfl_xor_sync(0xffffffffu, lsum, 2);
            if (qd == 0) {
                m_sm[r] = m_new;
                l_sm[r] = l_sm[r] * alpha + lsum;
            }
            // rescale O row segment
            float* orow = &Os[r * FST + qd * 16];
#pragma unroll
            for (int j = 0; j < 16; j++) orow[j] *= alpha;
        }
        __syncthreads();

        // O += P V : warp covers rows rg*16..+16, d cols half*32..+32
        wmma::fragment<wmma::accumulator, 16, 16, 16, float> ofrag[2];
#pragma unroll
        for (int nt = 0; nt < 2; nt++)
            wmma::load_matrix_sync(ofrag[nt], &Os[(rg * 16) * FST + half * 32 + nt * 16],
                                   FST, wmma::mem_row_major);
#pragma unroll
        for (int kk = 0; kk < 4; kk++) {
            wmma::fragment<wmma::matrix_a, 16, 16, 16, bf16, wmma::row_major> aph, apl;
            wmma::load_matrix_sync(aph, &Ps_h[(rg * 16) * FST + kk * 16], FST);
            wmma::load_matrix_sync(apl, &Ps_l[(rg * 16) * FST + kk * 16], FST);
#pragma unroll
            for (int nt = 0; nt < 2; nt++) {
                wmma::fragment<wmma::matrix_b, 16, 16, 16, bf16, wmma::row_major> vh, vl;
                int dcol = half * 32 + nt * 16;
                wmma::load_matrix_sync(vh, &Vs_h[(kk * 16) * FST + dcol], FST);
                wmma::load_matrix_sync(vl, &Vs_l[(kk * 16) * FST + dcol], FST);
                wmma::mma_sync(ofrag[nt], aph, vl, ofrag[nt]);
                wmma::mma_sync(ofrag[nt], apl, vh, ofrag[nt]);
                wmma::mma_sync(ofrag[nt], aph, vh, ofrag[nt]);
            }
        }
#pragma unroll
        for (int nt = 0; nt < 2; nt++)
            wmma::store_matrix_sync(&Os[(rg * 16) * FST + half * 32 + nt * 16],
                                    ofrag[nt], FST, wmma::mem_row_major);
        __syncthreads();
    }

    // normalize and write out
    for (int i = tid; i < 64 * 16; i += 256) {
        int rr = i >> 4, cc = (i & 15) << 2;
        float inv = 1.f / l_sm[rr];
        float4 ov = *(float4*)&Os[rr * FST + cc];
        ov.x *= inv; ov.y *= inv; ov.z *= inv; ov.w *= inv;
        *(float4*)(Og + (size_t)(q0 + rr) * NDH + cc) = ov;
    }
}

// ---------------- apply Mo to o, write token-major -----------------------------
__global__ void k_transform_o() {
    int idx = blockIdx.x * blockDim.x + threadIdx.x;
    if (idx >= NB * NH * NL * NG) return;
    int g = idx & 15;
    int l = (idx >> 4) & (NL - 1);
    int h = (idx >> 15) & 15;
    int b = idx >> 19;
    int c = l >> 8, p = l & 255;
    const float* Pi = g_Pi + (b * NC + c) * 16;
    float4 dv = *(const float4*)(g_Dt + (p * NG + g) * 4);
    float ca = dv.x, sa = dv.y, cb = dv.z, sb = dv.w;

    float4 t = *(const float4*)(g_oT + ((size_t)(b * NH + h) * NL + l) * NDH + g * 4);
    float z0 = Pi[0]  * t.x + Pi[1]  * t.y + Pi[2]  * t.z + Pi[3]  * t.w;
    float z1 = Pi[4]  * t.x + Pi[5]  * t.y + Pi[6]  * t.z + Pi[7]  * t.w;
    float z2 = Pi[8]  * t.x + Pi[9]  * t.y + Pi[10] * t.z + Pi[11] * t.w;
    float z3 = Pi[12] * t.x + Pi[13] * t.y + Pi[14] * t.z + Pi[15] * t.w;
    float4 o;
    o.x =  ca * z0 + sa * z1;
    o.y = -sa * z0 + ca * z1;
    o.z =  cb * z2 + sb * z3;
    o.w = -sb * z2 + cb * z3;
    *(float4*)(g_oTok + (size_t)(b * NL + l) * NDM + h * NDH + g * 4) = o;
}

// ---------------- launch --------------------------------------------------------
extern "C" void kernel_launch(void* const* d_in, const int* in_sizes, int n_in,
                              void* d_out, int out_size) {
    (void)in_sizes; (void)n_in; (void)out_size;
    const float* x     = (const float*)d_in[0];
    const float* vm    = (const float*)d_in[1];
    const float* Km    = (const float*)d_in[2];
    const float* wqkv  = (const float*)d_in[3];
    const float* wproj = (const float*)d_in[4];
    float* out = (float*)d_out;

    cudaFuncSetAttribute(k_flash, cudaFuncAttributeMaxDynamicSharedMemorySize, FLASH_SMEM);

    prope_mats<<<1, 32>>>(vm, Km);
    prope_dtab<<<16, 256>>>();
    k_gemm_qkv<<<dim3(3 * NDM / 128, NB * NL / 128), 256>>>(x, wqkv);
    k_transform_qkv<<<(NB * NH * NL * NG) / 256, 256>>>();
    k_flash<<<dim3(NL / 64, NB * NH), 256, FLASH_SMEM>>>();
    k_transform_o<<<(NB * NH * NL * NG) / 256, 256>>>();
    k_gemm_proj<<<dim3(NDM / 128, NB * NL / 128), 256>>>(wproj, out);
}

// round 9
// speedup vs baseline: 1.7729x; 1.0016x over previous
#include <cuda_runtime.h>
#include <cuda_bf16.h>
#include <mma.h>
#include <math.h>

using namespace nvcuda;

#define NB 2
#define NL 2048
#define NDM 1024
#define NH 16
#define NDH 64
#define NC 8
#define NPC 256
#define NG 16

typedef __nv_bfloat16 bf16;

// ---------------- scratch (device globals; no allocation allowed) -------------
__device__ float g_qkv[NB * NL * 3 * NDM];   // (B, L, 3, H, DH)
__device__ float g_qT[NB * NH * NL * NDH];   // (B, H, L, DH)
__device__ float g_kT[NB * NH * NL * NDH];
__device__ float g_vT[NB * NH * NL * NDH];
__device__ float g_oT[NB * NH * NL * NDH];
__device__ float g_oTok[NB * NL * NDM];      // (B, L, H*DH)
__device__ float g_P [NB * NC * 16];
__device__ float g_Pi[NB * NC * 16];
__device__ float g_Dt[NPC * NG * 4];         // (p, g) -> ca, sa, cb, sb

__device__ __forceinline__ void split_bf16(float x, bf16& h, bf16& l) {
    h = __float2bfloat16(x);
    l = __float2bfloat16(x - __bfloat162float(h));
}

// ---------------- per-camera P and P^{-1} -------------------------------------
__global__ void prope_mats(const float* __restrict__ vm, const float* __restrict__ Km) {
    int i = threadIdx.x;
    if (i >= NB * NC) return;
    const float* V = vm + i * 16;
    const float* Kc = Km + i * 9;
    double P[16];
    for (int r = 0; r < 3; r++)
        for (int j = 0; j < 4; j++) {
            double s = 0.0;
            for (int m = 0; m < 3; m++) s += (double)Kc[r * 3 + m] * (double)V[m * 4 + j];
            P[r * 4 + j] = s;
        }
    P[12] = V[12]; P[13] = V[13]; P[14] = V[14]; P[15] = V[15];
    for (int t = 0; t < 16; t++) g_P[i * 16 + t] = (float)P[t];

    double a00 = P[0], a01 = P[1], a02 = P[2];
    double a10 = P[4], a11 = P[5], a12 = P[6];
    double a20 = P[8], a21 = P[9], a22 = P[10];
    double c00 =  a11 * a22 - a12 * a21;
    double c01 = -(a10 * a22 - a12 * a20);
    double c02 =  a10 * a21 - a11 * a20;
    double det = a00 * c00 + a01 * c01 + a02 * c02;
    double id = 1.0 / det;
    double i00 = c00 * id;
    double i01 = (a02 * a21 - a01 * a22) * id;
    double i02 = (a01 * a12 - a02 * a11) * id;
    double i10 = c01 * id;
    double i11 = (a00 * a22 - a02 * a20) * id;
    double i12 = (a02 * a10 - a00 * a12) * id;
    double i20 = c02 * id;
    double i21 = (a01 * a20 - a00 * a21) * id;
    double i22 = (a00 * a11 - a01 * a10) * id;
    double b0 = P[3], b1 = P[7], b2 = P[11];
    double Pi[16] = { i00, i01, i02, -(i00 * b0 + i01 * b1 + i02 * b2),
                      i10, i11, i12, -(i10 * b0 + i11 * b1 + i12 * b2),
                      i20, i21, i22, -(i20 * b0 + i21 * b1 + i22 * b2),
                      0.0, 0.0, 0.0, 1.0 };
    for (int t = 0; t < 16; t++) g_Pi[i * 16 + t] = (float)Pi[t];
}

// ---------------- RoPE rotation table -----------------------------------------
__global__ void prope_dtab() {
    int idx = blockIdx.x * blockDim.x + threadIdx.x;
    if (idx >= NPC * NG) return;
    int p = idx >> 4, g = idx & 15;
    float u = ((p & 15) + 0.5f) * 16.0f;
    float v = ((p >> 4) + 0.5f) * 16.0f;
    float freq = (float)pow(10000.0, -(double)g / 16.0);
    float tu = u * freq;
    float tv = v * freq;
    g_Dt[idx * 4 + 0] = (float)cos((double)tu);
    g_Dt[idx * 4 + 1] = (float)sin((double)tu);
    g_Dt[idx * 4 + 2] = (float)cos((double)tv);
    g_Dt[idx * 4 + 3] = (float)sin((double)tv);
}

// ---------------- bf16x3 wmma GEMM: C[m][n] = sum_k A[m][k]*B[n][k] ------------
// Block tile 128x128, k-tile 32 (2 x k16). 8 warps: 2(m) x 4(n); warp tile 64x32.
#define GST 40   // bf16 smem stride: 32 k + 8 pad (80 bytes/row, 16B aligned)

__device__ __forceinline__ void gemm_bf16x3_body(const float* __restrict__ A,
                                                 const float* __restrict__ Bw,
                                                 float* __restrict__ C, int N, int K) {
    __shared__ bf16 As_h[128 * GST];
    __shared__ bf16 As_l[128 * GST];
    __shared__ bf16 Bs_h[128 * GST];
    __shared__ bf16 Bs_l[128 * GST];
    const int tid = threadIdx.x;
    const int wid = tid >> 5;
    const int wm = wid >> 2;            // 0..1
    const int wn = wid & 3;             // 0..3
    const int m0 = blockIdx.y * 128;
    const int n0 = blockIdx.x * 128;

    wmma::fragment<wmma::accumulator, 16, 16, 16, float> acc[4][2];
#pragma unroll
    for (int mi = 0; mi < 4; mi++)
#pragma unroll
        for (int ni = 0; ni < 2; ni++) wmma::fill_fragment(acc[mi][ni], 0.0f);

    for (int k0 = 0; k0 < K; k0 += 32) {
        __syncthreads();
#pragma unroll
        for (int i = tid; i < 1024; i += 256) {
            int rr = i >> 3, kc = (i & 7) << 2;
            float4 av = *(const float4*)(A  + (size_t)(m0 + rr) * K + k0 + kc);
            float4 bv = *(const float4*)(Bw + (size_t)(n0 + rr) * K + k0 + kc);
            bf16 h0, l0, h1, l1, h2, l2, h3, l3;
            split_bf16(av.x, h0, l0); split_bf16(av.y, h1, l1);
            split_bf16(av.z, h2, l2); split_bf16(av.w, h3, l3);
            As_h[rr * GST + kc] = h0; As_h[rr * GST + kc + 1] = h1;
            As_h[rr * GST + kc + 2] = h2; As_h[rr * GST + kc + 3] = h3;
            As_l[rr * GST + kc] = l0; As_l[rr * GST + kc + 1] = l1;
            As_l[rr * GST + kc + 2] = l2; As_l[rr * GST + kc + 3] = l3;
            split_bf16(bv.x, h0, l0); split_bf16(bv.y, h1, l1);
            split_bf16(bv.z, h2, l2); split_bf16(bv.w, h3, l3);
            Bs_h[rr * GST + kc] = h0; Bs_h[rr * GST + kc + 1] = h1;
            Bs_h[rr * GST + kc + 2] = h2; Bs_h[rr * GST + kc + 3] = h3;
            Bs_l[rr * GST + kc] = l0; Bs_l[rr * GST + kc + 1] = l1;
            Bs_l[rr * GST + kc + 2] = l2; Bs_l[rr * GST + kc + 3] = l3;
        }
        __syncthreads();
#pragma unroll
        for (int kk = 0; kk < 2; kk++) {
            wmma::fragment<wmma::matrix_a, 16, 16, 16, bf16, wmma::row_major> ah[4], al[4];
#pragma unroll
            for (int mi = 0; mi < 4; mi++) {
                wmma::load_matrix_sync(ah[mi], &As_h[(wm * 64 + mi * 16) * GST + kk * 16], GST);
                wmma::load_matrix_sync(al[mi], &As_l[(wm * 64 + mi * 16) * GST + kk * 16], GST);
            }
#pragma unroll
            for (int ni = 0; ni < 2; ni++) {
                wmma::fragment<wmma::matrix_b, 16, 16, 16, bf16, wmma::col_major> bh, bl;
                wmma::load_matrix_sync(bh, &Bs_h[(wn * 32 + ni * 16) * GST + kk * 16], GST);
                wmma::load_matrix_sync(bl, &Bs_l[(wn * 32 + ni * 16) * GST + kk * 16], GST);
#pragma unroll
                for (int mi = 0; mi < 4; mi++) {
                    wmma::mma_sync(acc[mi][ni], ah[mi], bl, acc[mi][ni]);
                    wmma::mma_sync(acc[mi][ni], al[mi], bh, acc[mi][ni]);
                    wmma::mma_sync(acc[mi][ni], ah[mi], bh, acc[mi][ni]);
                }
            }
        }
    }
#pragma unroll
    for (int mi = 0; mi < 4; mi++)
#pragma unroll
        for (int ni = 0; ni < 2; ni++)
            wmma::store_matrix_sync(C + (size_t)(m0 + wm * 64 + mi * 16) * N + n0 + wn * 32 + ni * 16,
                                    acc[mi][ni], N, wmma::mem_row_major);
}

__global__ void __launch_bounds__(256) k_gemm_qkv(const float* __restrict__ x,
                                                  const float* __restrict__ w) {
    gemm_bf16x3_body(x, w, g_qkv, 3 * NDM, NDM);
}
__global__ void __launch_bounds__(256) k_gemm_proj(const float* __restrict__ w,
                                                   float* __restrict__ out) {
    gemm_bf16x3_body(g_oTok, w, out, NDM, NDM);
}

// ---------------- apply Mq / Mkv to q, k, v ------------------------------------
__global__ void k_transform_qkv() {
    int idx = blockIdx.x * blockDim.x + threadIdx.x;
    if (idx >= NB * NH * NL * NG) return;
    int g = idx & 15;
    int l = (idx >> 4) & (NL - 1);
    int h = (idx >> 15) & 15;
    int b = idx >> 19;
    int c = l >> 8, p = l & 255;
    const float* Pm = g_P  + (b * NC + c) * 16;
    const float* Pi = g_Pi + (b * NC + c) * 16;
    float4 dv = *(const float4*)(g_Dt + (p * NG + g) * 4);
    float ca = dv.x, sa = dv.y, cb = dv.z, sb = dv.w;

    size_t base = ((size_t)(b * NL + l) * 3) * NDM + h * NDH + g * 4;
    size_t obase = ((size_t)(b * NH + h) * NL + l) * NDH + g * 4;

    {
        float4 t = *(const float4*)(g_qkv + base);
        float d0 = ca * t.x - sa * t.y, d1 = sa * t.x + ca * t.y;
        float d2 = cb * t.z - sb * t.w, d3 = sb * t.z + cb * t.w;
        float4 o;
        o.x = Pi[0] * d0 + Pi[4] * d1 + Pi[8]  * d2 + Pi[12] * d3;
        o.y = Pi[1] * d0 + Pi[5] * d1 + Pi[9]  * d2 + Pi[13] * d3;
        o.z = Pi[2] * d0 + Pi[6] * d1 + Pi[10] * d2 + Pi[14] * d3;
        o.w = Pi[3] * d0 + Pi[7] * d1 + Pi[11] * d2 + Pi[15] * d3;
        *(float4*)(g_qT + obase) = o;
    }
    {
        float4 t = *(const float4*)(g_qkv + base + NDM);
        float d0 = ca * t.x - sa * t.y, d1 = sa * t.x + ca * t.y;
        float d2 = cb * t.z - sb * t.w, d3 = sb * t.z + cb * t.w;
        float4 o;
        o.x = Pm[0]  * d0 + Pm[1]  * d1 + Pm[2]  * d2 + Pm[3]  * d3;
        o.y = Pm[4]  * d0 + Pm[5]  * d1 + Pm[6]  * d2 + Pm[7]  * d3;
        o.z = Pm[8]  * d0 + Pm[9]  * d1 + Pm[10] * d2 + Pm[11] * d3;
        o.w = Pm[12] * d0 + Pm[13] * d1 + Pm[14] * d2 + Pm[15] * d3;
        *(float4*)(g_kT + obase) = o;
    }
    {
        float4 t = *(const float4*)(g_qkv + base + 2 * NDM);
        float d0 = ca * t.x - sa * t.y, d1 = sa * t.x + ca * t.y;
        float d2 = cb * t.z - sb * t.w, d3 = sb * t.z + cb * t.w;
        float4 o;
        o.x = Pm[0]  * d0 + Pm[1]  * d1 + Pm[2]  * d2 + Pm[3]  * d3;
        o.y = Pm[4]  * d0 + Pm[5]  * d1 + Pm[6]  * d2 + Pm[7]  * d3;
        o.z = Pm[8]  * d0 + Pm[9]  * d1 + Pm[10] * d2 + Pm[11] * d3;
        o.w = Pm[12] * d0 + Pm[13] * d1 + Pm[14] * d2 + Pm[15] * d3;
        *(float4*)(g_vT + obase) = o;
    }
}

// ---------------- flash attention (bf16x3 wmma, BM=64 q rows, BN=64 kv) --------
// 8 warps: warp w -> row-group rg = w>>1 (16 q rows), half = w&1 (32-col half).
// bf16 tiles stride 72 (144 B/row, 16B aligned, mult of 8 elems).
#define FST 72
#define FL_T  (64 * FST)          // elements per 64-row tile

#define OFF_KH 0
#define OFF_KL (OFF_KH + FL_T)
#define OFF_VH (OFF_KL + FL_T)
#define OFF_VL (OFF_VH + FL_T)
#define OFF_QH (OFF_VL + FL_T)    // reused as P_hi after Q fragments loaded
#define OFF_QL (OFF_QH + FL_T)    // reused as P_lo
#define BF_ELEMS (OFF_QL + FL_T)

#define FLASH_SMEM (BF_ELEMS * 2 + (2 * FL_T + 128) * 4)

__global__ void __launch_bounds__(256) k_flash() {
    extern __shared__ char fshraw[];
    bf16*  bfb  = (bf16*)fshraw;
    float* Ss   = (float*)(fshraw + BF_ELEMS * 2);
    float* Os   = Ss + FL_T;
    float* m_sm = Os + FL_T;
    float* l_sm = m_sm + 64;

    bf16* Ks_h = bfb + OFF_KH; bf16* Ks_l = bfb + OFF_KL;
    bf16* Vs_h = bfb + OFF_VH; bf16* Vs_l = bfb + OFF_VL;
    bf16* Qs_h = bfb + OFF_QH; bf16* Qs_l = bfb + OFF_QL;
    bf16* Ps_h = Qs_h;         bf16* Ps_l = Qs_l;

    const int tid = threadIdx.x;
    const int lane = tid & 31;
    const int w = tid >> 5;
    const int rg = w >> 1;           // 0..3: q rows rg*16..+16
    const int half = w & 1;          // 0..1: 32-col half

    const int bh = blockIdx.y;
    const int q0 = blockIdx.x * 64;

    const float* Qg = g_qT + (size_t)bh * NL * NDH;
    const float* Kg = g_kT + (size_t)bh * NL * NDH;
    const float* Vg = g_vT + (size_t)bh * NL * NDH;
    float* Og       = g_oT + (size_t)bh * NL * NDH;

    // init O, m, l; stage Q split
    for (int i = tid; i < FL_T; i += 256) Os[i] = 0.f;
    if (tid < 64) { m_sm[tid] = -1e30f; l_sm[tid] = 0.f; }
    for (int i = tid; i < 64 * 16; i += 256) {
        int rr = i >> 4, cc = (i & 15) << 2;
        float4 t = *(const float4*)(Qg + (size_t)(q0 + rr) * NDH + cc);
        bf16 h, l;
        split_bf16(t.x, h, l); Qs_h[rr * FST + cc]     = h; Qs_l[rr * FST + cc]     = l;
        split_bf16(t.y, h, l); Qs_h[rr * FST + cc + 1] = h; Qs_l[rr * FST + cc + 1] = l;
        split_bf16(t.z, h, l); Qs_h[rr * FST + cc + 2] = h; Qs_l[rr * FST + cc + 2] = l;
        split_bf16(t.w, h, l); Qs_h[rr * FST + cc + 3] = h; Qs_l[rr * FST + cc + 3] = l;
    }
    __syncthreads();

    // preload Q fragments (4 k-steps over d=64)
    wmma::fragment<wmma::matrix_a, 16, 16, 16, bf16, wmma::row_major> aqh[4], aql[4];
#pragma unroll
    for (int kk = 0; kk < 4; kk++) {
        wmma::load_matrix_sync(aqh[kk], &Qs_h[(rg * 16) * FST + kk * 16], FST);
        wmma::load_matrix_sync(aql[kk], &Qs_l[(rg * 16) * FST + kk * 16], FST);
    }
    __syncthreads();   // everyone has fragments; Qs can be reused as Ps

    for (int n0 = 0; n0 < NL; n0 += 64) {
        // load + split K/V tile 64x64
        for (int i = tid; i < 64 * 16; i += 256) {
            int rr = i >> 4, cc = (i & 15) << 2;
            float4 kt = *(const float4*)(Kg + (size_t)(n0 + rr) * NDH + cc);
            float4 vt = *(const float4*)(Vg + (size_t)(n0 + rr) * NDH + cc);
            bf16 h, l;
            split_bf16(kt.x, h, l); Ks_h[rr * FST + cc]     = h; Ks_l[rr * FST + cc]     = l;
            split_bf16(kt.y, h, l); Ks_h[rr * FST + cc + 1] = h; Ks_l[rr * FST + cc + 1] = l;
            split_bf16(kt.z, h, l); Ks_h[rr * FST + cc + 2] = h; Ks_l[rr * FST + cc + 2] = l;
            split_bf16(kt.w, h, l); Ks_h[rr * FST + cc + 3] = h; Ks_l[rr * FST + cc + 3] = l;
            split_bf16(vt.x, h, l); Vs_h[rr * FST + cc]     = h; Vs_l[rr * FST + cc]     = l;
            split_bf16(vt.y, h, l); Vs_h[rr * FST + cc + 1] = h; Vs_l[rr * FST + cc + 1] = l;
            split_bf16(vt.z, h, l); Vs_h[rr * FST + cc + 2] = h; Vs_l[rr * FST + cc + 2] = l;
            split_bf16(vt.w, h, l); Vs_h[rr * FST + cc + 3] = h; Vs_l[rr * FST + cc + 3] = l;
        }
        __syncthreads();

        // S = Q K^T : warp covers rows rg*16..+16, kv cols half*32..+32
        wmma::fragment<wmma::accumulator, 16, 16, 16, float> sfrag[2];
#pragma unroll
        for (int nt = 0; nt < 2; nt++) wmma::fill_fragment(sfrag[nt], 0.f);
#pragma unroll
        for (int kk = 0; kk < 4; kk++) {
#pragma unroll
            for (int nt = 0; nt < 2; nt++) {
                wmma::fragment<wmma::matrix_b, 16, 16, 16, bf16, wmma::col_major> bh, bl;
                int kvrow = half * 32 + nt * 16;
                wmma::load_matrix_sync(bh, &Ks_h[kvrow * FST + kk * 16], FST);
                wmma::load_matrix_sync(bl, &Ks_l[kvrow * FST + kk * 16], FST);
                wmma::mma_sync(sfrag[nt], aqh[kk], bl, sfrag[nt]);
                wmma::mma_sync(sfrag[nt], aql[kk], bh, sfrag[nt]);
                wmma::mma_sync(sfrag[nt], aqh[kk], bh, sfrag[nt]);
            }
        }
#pragma unroll
        for (int nt = 0; nt < 2; nt++)
            wmma::store_matrix_sync(&Ss[(rg * 16) * FST + half * 32 + nt * 16],
                                    sfrag[nt], FST, wmma::mem_row_major);
        __syncthreads();

        // online softmax: 4 threads per row, 16 cols each
        {
            int r = tid >> 2;            // 0..63
            int qd = tid & 3;
            float* srow = &Ss[r * FST + qd * 16];
            float sv[16];
            float mloc = -1e30f;
#pragma unroll
            for (int j = 0; j < 16; j++) {
                sv[j] = srow[j] * 0.125f;
                mloc = fmaxf(mloc, sv[j]);
            }
            mloc = fmaxf(mloc, __shfl_xor_sync(0xffffffffu, mloc, 1));
            mloc = fmaxf(mloc, __shfl_xor_sync(0xffffffffu, mloc, 2));
            float m_old = m_sm[r];
            float m_new = fmaxf(m_old, mloc);
            float alpha = __expf(m_old - m_new);
            float lsum = 0.f;
            bf16* ph = &Ps_h[r * FST + qd * 16];
            bf16* pl = &Ps_l[r * FST + qd * 16];
#pragma unroll
            for (int j = 0; j < 16; j++) {
                float p = __expf(sv[j] - m_new);
                lsum += p;
                bf16 h, l;
                split_bf16(p, h, l);
                ph[j] = h; pl[j] = l;
            }
            lsum += __shfl_xor_sync(0xffffffffu, lsum, 1);
            lsum += __shfl_xor_sync(0xffffffffu, lsum, 2);
            if (qd == 0) {
                m_sm[r] = m_new;
                l_sm[r] = l_sm[r] * alpha + lsum;
            }
            // rescale O row segment
            float* orow = &Os[r * FST + qd * 16];
#pragma unroll
            for (int j = 0; j < 16; j++) orow[j] *= alpha;
        }
        __syncthreads();

        // O += P V : warp covers rows rg*16..+16, d cols half*32..+32
        wmma::fragment<wmma::accumulator, 16, 16, 16, float> ofrag[2];
#pragma unroll
        for (int nt = 0; nt < 2; nt++)
            wmma::load_matrix_sync(ofrag[nt], &Os[(rg * 16) * FST + half * 32 + nt * 16],
                                   FST, wmma::mem_row_major);
#pragma unroll
        for (int kk = 0; kk < 4; kk++) {
            wmma::fragment<wmma::matrix_a, 16, 16, 16, bf16, wmma::row_major> aph, apl;
            wmma::load_matrix_sync(aph, &Ps_h[(rg * 16) * FST + kk * 16], FST);
            wmma::load_matrix_sync(apl, &Ps_l[(rg * 16) * FST + kk * 16], FST);
#pragma unroll
            for (int nt = 0; nt < 2; nt++) {
                wmma::fragment<wmma::matrix_b, 16, 16, 16, bf16, wmma::row_major> vh, vl;
                int dcol = half * 32 + nt * 16;
                wmma::load_matrix_sync(vh, &Vs_h[(kk * 16) * FST + dcol], FST);
                wmma::load_matrix_sync(vl, &Vs_l[(kk * 16) * FST + dcol], FST);
                wmma::mma_sync(ofrag[nt], aph, vl, ofrag[nt]);
                wmma::mma_sync(ofrag[nt], apl, vh, ofrag[nt]);
                wmma::mma_sync(ofrag[nt], aph, vh, ofrag[nt]);
            }
        }
#pragma unroll
        for (int nt = 0; nt < 2; nt++)
            wmma::store_matrix_sync(&Os[(rg * 16) * FST + half * 32 + nt * 16],
                                    ofrag[nt], FST, wmma::mem_row_major);
        __syncthreads();
    }

    // normalize and write out
    for (int i = tid; i < 64 * 16; i += 256) {
        int rr = i >> 4, cc = (i & 15) << 2;
        float inv = 1.f / l_sm[rr];
        float4 ov = *(float4*)&Os[rr * FST + cc];
        ov.x *= inv; ov.y *= inv; ov.z *= inv; ov.w *= inv;
        *(float4*)(Og + (size_t)(q0 + rr) * NDH + cc) = ov;
    }
}

// ---------------- apply Mo to o, write token-major -----------------------------
__global__ void k_transform_o() {
    int idx = blockIdx.x * blockDim.x + threadIdx.x;
    if (idx >= NB * NH * NL * NG) return;
    int g = idx & 15;
    int l = (idx >> 4) & (NL - 1);
    int h = (idx >> 15) & 15;
    int b = idx >> 19;
    int c = l >> 8, p = l & 255;
    const float* Pi = g_Pi + (b * NC + c) * 16;
    float4 dv = *(const float4*)(g_Dt + (p * NG + g) * 4);
    float ca = dv.x, sa = dv.y, cb = dv.z, sb = dv.w;

    float4 t = *(const float4*)(g_oT + ((size_t)(b * NH + h) * NL + l) * NDH + g * 4);
    float z0 = Pi[0]  * t.x + Pi[1]  * t.y + Pi[2]  * t.z + Pi[3]  * t.w;
    float z1 = Pi[4]  * t.x + Pi[5]  * t.y + Pi[6]  * t.z + Pi[7]  * t.w;
    float z2 = Pi[8]  * t.x + Pi[9]  * t.y + Pi[10] * t.z + Pi[11] * t.w;
    float z3 = Pi[12] * t.x + Pi[13] * t.y + Pi[14] * t.z + Pi[15] * t.w;
    float4 o;
    o.x =  ca * z0 + sa * z1;
    o.y = -sa * z0 + ca * z1;
    o.z =  cb * z2 + sb * z3;
    o.w = -sb * z2 + cb * z3;
    *(float4*)(g_oTok + (size_t)(b * NL + l) * NDM + h * NDH + g * 4) = o;
}

// ---------------- launch --------------------------------------------------------
extern "C" void kernel_launch(void* const* d_in, const int* in_sizes, int n_in,
                              void* d_out, int out_size) {
    (void)in_sizes; (void)n_in; (void)out_size;
    const float* x     = (const float*)d_in[0];
    const float* vm    = (const float*)d_in[1];
    const float* Km    = (const float*)d_in[2];
    const float* wqkv  = (const float*)d_in[3];
    const float* wproj = (const float*)d_in[4];
    float* out = (float*)d_out;

    cudaFuncSetAttribute(k_flash, cudaFuncAttributeMaxDynamicSharedMemorySize, FLASH_SMEM);

    prope_mats<<<1, 32>>>(vm, Km);
    prope_dtab<<<16, 256>>>();
    k_gemm_qkv<<<dim3(3 * NDM / 128, NB * NL / 128), 256>>>(x, wqkv);
    k_transform_qkv<<<(NB * NH * NL * NG) / 256, 256>>>();
    k_flash<<<dim3(NL / 64, NB * NH), 256, FLASH_SMEM>>>();
    k_transform_o<<<(NB * NH * NL * NG) / 256, 256>>>();
    k_gemm_proj<<<dim3(NDM / 128, NB * NL / 128), 256>>>(wproj, out);
}

// round 13
// speedup vs baseline: 1.8836x; 1.0624x over previous
#include <cuda_runtime.h>
#include <cuda_bf16.h>
#include <mma.h>
#include <math.h>

using namespace nvcuda;

#define NB 2
#define NL 2048
#define NDM 1024
#define NH 16
#define NDH 64
#define NC 8
#define NPC 256
#define NG 16

typedef __nv_bfloat16 bf16;

// ---------------- scratch (device globals; no allocation allowed) -------------
__device__ float g_qkv[NB * NL * 3 * NDM];   // (B, L, 3, H, DH) fp32 (GEMM out)
__device__ float g_oT[NB * NH * NL * NDH];   // attention out fp32
__device__ float g_P [NB * NC * 16];
__device__ float g_Pi[NB * NC * 16];
__device__ float g_Dt[NPC * NG * 4];

// pre-split bf16 hi/lo operands
__device__ bf16 g_xh[NB * NL * NDM],      g_xl[NB * NL * NDM];
__device__ bf16 g_wqh[3 * NDM * NDM],     g_wql[3 * NDM * NDM];
__device__ bf16 g_wph[NDM * NDM],         g_wpl[NDM * NDM];
__device__ bf16 g_qh[NB * NH * NL * NDH], g_ql[NB * NH * NL * NDH];
__device__ bf16 g_kh[NB * NH * NL * NDH], g_kl[NB * NH * NL * NDH];
__device__ bf16 g_vh[NB * NH * NL * NDH], g_vl[NB * NH * NL * NDH];
__device__ bf16 g_oh[NB * NL * NDM],      g_ol[NB * NL * NDM];

__device__ __forceinline__ void split_bf16(float x, bf16& h, bf16& l) {
    h = __float2bfloat16(x);
    l = __float2bfloat16(x - __bfloat162float(h));
}
__device__ __forceinline__ unsigned pack2(bf16 a, bf16 b) {
    return (unsigned)__bfloat16_as_ushort(a) | ((unsigned)__bfloat16_as_ushort(b) << 16);
}
__device__ __forceinline__ void split4(float4 v, uint2& uh, uint2& ul) {
    bf16 h0, l0, h1, l1, h2, l2, h3, l3;
    split_bf16(v.x, h0, l0); split_bf16(v.y, h1, l1);
    split_bf16(v.z, h2, l2); split_bf16(v.w, h3, l3);
    uh.x = pack2(h0, h1); uh.y = pack2(h2, h3);
    ul.x = pack2(l0, l1); ul.y = pack2(l2, l3);
}

// ---------------- split fp32 array -> bf16 hi/lo ------------------------------
__global__ void k_split(const float* __restrict__ s, bf16* __restrict__ h,
                        bf16* __restrict__ l, int n4) {
    int i = blockIdx.x * blockDim.x + threadIdx.x;
    if (i >= n4) return;
    float4 v = ((const float4*)s)[i];
    uint2 uh, ul;
    split4(v, uh, ul);
    ((uint2*)h)[i] = uh;
    ((uint2*)l)[i] = ul;
}

// ---------------- per-camera P and P^{-1} -------------------------------------
__global__ void prope_mats(const float* __restrict__ vm, const float* __restrict__ Km) {
    int i = threadIdx.x;
    if (i >= NB * NC) return;
    const float* V = vm + i * 16;
    const float* Kc = Km + i * 9;
    double P[16];
    for (int r = 0; r < 3; r++)
        for (int j = 0; j < 4; j++) {
            double s = 0.0;
            for (int m = 0; m < 3; m++) s += (double)Kc[r * 3 + m] * (double)V[m * 4 + j];
            P[r * 4 + j] = s;
        }
    P[12] = V[12]; P[13] = V[13]; P[14] = V[14]; P[15] = V[15];
    for (int t = 0; t < 16; t++) g_P[i * 16 + t] = (float)P[t];

    double a00 = P[0], a01 = P[1], a02 = P[2];
    double a10 = P[4], a11 = P[5], a12 = P[6];
    double a20 = P[8], a21 = P[9], a22 = P[10];
    double c00 =  a11 * a22 - a12 * a21;
    double c01 = -(a10 * a22 - a12 * a20);
    double c02 =  a10 * a21 - a11 * a20;
    double det = a00 * c00 + a01 * c01 + a02 * c02;
    double id = 1.0 / det;
    double i00 = c00 * id;
    double i01 = (a02 * a21 - a01 * a22) * id;
    double i02 = (a01 * a12 - a02 * a11) * id;
    double i10 = c01 * id;
    double i11 = (a00 * a22 - a02 * a20) * id;
    double i12 = (a02 * a10 - a00 * a12) * id;
    double i20 = c02 * id;
    double i21 = (a01 * a20 - a00 * a21) * id;
    double i22 = (a00 * a11 - a01 * a10) * id;
    double b0 = P[3], b1 = P[7], b2 = P[11];
    double Pi[16] = { i00, i01, i02, -(i00 * b0 + i01 * b1 + i02 * b2),
                      i10, i11, i12, -(i10 * b0 + i11 * b1 + i12 * b2),
                      i20, i21, i22, -(i20 * b0 + i21 * b1 + i22 * b2),
                      0.0, 0.0, 0.0, 1.0 };
    for (int t = 0; t < 16; t++) g_Pi[i * 16 + t] = (float)Pi[t];
}

// ---------------- RoPE rotation table -----------------------------------------
__global__ void prope_dtab() {
    int idx = blockIdx.x * blockDim.x + threadIdx.x;
    if (idx >= NPC * NG) return;
    int p = idx >> 4, g = idx & 15;
    float u = ((p & 15) + 0.5f) * 16.0f;
    float v = ((p >> 4) + 0.5f) * 16.0f;
    float freq = (float)pow(10000.0, -(double)g / 16.0);
    float tu = u * freq;
    float tv = v * freq;
    g_Dt[idx * 4 + 0] = (float)cos((double)tu);
    g_Dt[idx * 4 + 1] = (float)sin((double)tu);
    g_Dt[idx * 4 + 2] = (float)cos((double)tv);
    g_Dt[idx * 4 + 3] = (float)sin((double)tv);
}

// ---------------- bf16x3 wmma GEMM on pre-split operands ----------------------
// C[m][n] = sum_k A[m][k]*B[n][k]. Block 128x128, k-tile 32. 8 warps 2x4.
#define GST 40

__device__ __forceinline__ void gemm_presplit(const bf16* __restrict__ Ah,
                                              const bf16* __restrict__ Al,
                                              const bf16* __restrict__ Bh,
                                              const bf16* __restrict__ Bl,
                                              float* __restrict__ C, int N, int K) {
    __shared__ bf16 smA_h[128 * GST];
    __shared__ bf16 smA_l[128 * GST];
    __shared__ bf16 smB_h[128 * GST];
    __shared__ bf16 smB_l[128 * GST];
    const int tid = threadIdx.x;
    const int wid = tid >> 5;
    const int wm = wid >> 2;
    const int wn = wid & 3;
    const int m0 = blockIdx.y * 128;
    const int n0 = blockIdx.x * 128;
    const int rr0 = tid >> 2;             // 0..63 (also +64)
    const int kc0 = (tid & 3) * 8;

    wmma::fragment<wmma::accumulator, 16, 16, 16, float> acc[4][2];
#pragma unroll
    for (int mi = 0; mi < 4; mi++)
#pragma unroll
        for (int ni = 0; ni < 2; ni++) wmma::fill_fragment(acc[mi][ni], 0.0f);

    uint4 pa0h, pa1h, pa0l, pa1l, pb0h, pb1h, pb0l, pb1l;

    {
        size_t oa0 = (size_t)(m0 + rr0) * K + kc0;
        size_t oa1 = oa0 + (size_t)64 * K;
        size_t ob0 = (size_t)(n0 + rr0) * K + kc0;
        size_t ob1 = ob0 + (size_t)64 * K;
        pa0h = *(const uint4*)(Ah + oa0); pa1h = *(const uint4*)(Ah + oa1);
        pa0l = *(const uint4*)(Al + oa0); pa1l = *(const uint4*)(Al + oa1);
        pb0h = *(const uint4*)(Bh + ob0); pb1h = *(const uint4*)(Bh + ob1);
        pb0l = *(const uint4*)(Bl + ob0); pb1l = *(const uint4*)(Bl + ob1);
    }

    for (int k0 = 0; k0 < K; k0 += 32) {
        __syncthreads();
        *(uint4*)&smA_h[rr0 * GST + kc0]        = pa0h;
        *(uint4*)&smA_h[(rr0 + 64) * GST + kc0] = pa1h;
        *(uint4*)&smA_l[rr0 * GST + kc0]        = pa0l;
        *(uint4*)&smA_l[(rr0 + 64) * GST + kc0] = pa1l;
        *(uint4*)&smB_h[rr0 * GST + kc0]        = pb0h;
        *(uint4*)&smB_h[(rr0 + 64) * GST + kc0] = pb1h;
        *(uint4*)&smB_l[rr0 * GST + kc0]        = pb0l;
        *(uint4*)&smB_l[(rr0 + 64) * GST + kc0] = pb1l;
        __syncthreads();

        if (k0 + 32 < K) {
            size_t oa0 = (size_t)(m0 + rr0) * K + k0 + 32 + kc0;
            size_t oa1 = oa0 + (size_t)64 * K;
            size_t ob0 = (size_t)(n0 + rr0) * K + k0 + 32 + kc0;
            size_t ob1 = ob0 + (size_t)64 * K;
            pa0h = *(const uint4*)(Ah + oa0); pa1h = *(const uint4*)(Ah + oa1);
            pa0l = *(const uint4*)(Al + oa0); pa1l = *(const uint4*)(Al + oa1);
            pb0h = *(const uint4*)(Bh + ob0); pb1h = *(const uint4*)(Bh + ob1);
            pb0l = *(const uint4*)(Bl + ob0); pb1l = *(const uint4*)(Bl + ob1);
        }

#pragma unroll
        for (int kk = 0; kk < 2; kk++) {
            wmma::fragment<wmma::matrix_a, 16, 16, 16, bf16, wmma::row_major> ah[4], al[4];
#pragma unroll
            for (int mi = 0; mi < 4; mi++) {
                wmma::load_matrix_sync(ah[mi], &smA_h[(wm * 64 + mi * 16) * GST + kk * 16], GST);
                wmma::load_matrix_sync(al[mi], &smA_l[(wm * 64 + mi * 16) * GST + kk * 16], GST);
            }
#pragma unroll
            for (int ni = 0; ni < 2; ni++) {
                wmma::fragment<wmma::matrix_b, 16, 16, 16, bf16, wmma::col_major> bh, bl;
                wmma::load_matrix_sync(bh, &smB_h[(wn * 32 + ni * 16) * GST + kk * 16], GST);
                wmma::load_matrix_sync(bl, &smB_l[(wn * 32 + ni * 16) * GST + kk * 16], GST);
#pragma unroll
                for (int mi = 0; mi < 4; mi++) {
                    wmma::mma_sync(acc[mi][ni], ah[mi], bl, acc[mi][ni]);
                    wmma::mma_sync(acc[mi][ni], al[mi], bh, acc[mi][ni]);
                    wmma::mma_sync(acc[mi][ni], ah[mi], bh, acc[mi][ni]);
                }
            }
        }
    }
#pragma unroll
    for (int mi = 0; mi < 4; mi++)
#pragma unroll
        for (int ni = 0; ni < 2; ni++)
            wmma::store_matrix_sync(C + (size_t)(m0 + wm * 64 + mi * 16) * N + n0 + wn * 32 + ni * 16,
                                    acc[mi][ni], N, wmma::mem_row_major);
}

__global__ void __launch_bounds__(256, 2) k_gemm_qkv() {
    gemm_presplit(g_xh, g_xl, g_wqh, g_wql, g_qkv, 3 * NDM, NDM);
}
__global__ void __launch_bounds__(256, 2) k_gemm_proj(float* __restrict__ out) {
    gemm_presplit(g_oh, g_ol, g_wph, g_wpl, out, NDM, NDM);
}

// ---------------- apply Mq / Mkv; emit pre-split bf16 q,k,v --------------------
__global__ void k_transform_qkv() {
    int idx = blockIdx.x * blockDim.x + threadIdx.x;
    if (idx >= NB * NH * NL * NG) return;
    int g = idx & 15;
    int l = (idx >> 4) & (NL - 1);
    int h = (idx >> 15) & 15;
    int b = idx >> 19;
    int c = l >> 8, p = l & 255;
    const float* Pm = g_P  + (b * NC + c) * 16;
    const float* Pi = g_Pi + (b * NC + c) * 16;
    float4 dv = *(const float4*)(g_Dt + (p * NG + g) * 4);
    float ca = dv.x, sa = dv.y, cb = dv.z, sb = dv.w;

    size_t base = ((size_t)(b * NL + l) * 3) * NDM + h * NDH + g * 4;
    size_t obase = ((size_t)(b * NH + h) * NL + l) * NDH + g * 4;
    size_t ob2 = obase >> 2;   // uint2 index (4 bf16 per uint2)

    {
        float4 t = *(const float4*)(g_qkv + base);
        float d0 = ca * t.x - sa * t.y, d1 = sa * t.x + ca * t.y;
        float d2 = cb * t.z - sb * t.w, d3 = sb * t.z + cb * t.w;
        float4 o;
        o.x = Pi[0] * d0 + Pi[4] * d1 + Pi[8]  * d2 + Pi[12] * d3;
        o.y = Pi[1] * d0 + Pi[5] * d1 + Pi[9]  * d2 + Pi[13] * d3;
        o.z = Pi[2] * d0 + Pi[6] * d1 + Pi[10] * d2 + Pi[14] * d3;
        o.w = Pi[3] * d0 + Pi[7] * d1 + Pi[11] * d2 + Pi[15] * d3;
        uint2 uh, ul; split4(o, uh, ul);
        ((uint2*)g_qh)[ob2] = uh; ((uint2*)g_ql)[ob2] = ul;
    }
    {
        float4 t = *(const float4*)(g_qkv + base + NDM);
        float d0 = ca * t.x - sa * t.y, d1 = sa * t.x + ca * t.y;
        float d2 = cb * t.z - sb * t.w, d3 = sb * t.z + cb * t.w;
        float4 o;
        o.x = Pm[0]  * d0 + Pm[1]  * d1 + Pm[2]  * d2 + Pm[3]  * d3;
        o.y = Pm[4]  * d0 + Pm[5]  * d1 + Pm[6]  * d2 + Pm[7]  * d3;
        o.z = Pm[8]  * d0 + Pm[9]  * d1 + Pm[10] * d2 + Pm[11] * d3;
        o.w = Pm[12] * d0 + Pm[13] * d1 + Pm[14] * d2 + Pm[15] * d3;
        uint2 uh, ul; split4(o, uh, ul);
        ((uint2*)g_kh)[ob2] = uh; ((uint2*)g_kl)[ob2] = ul;
    }
    {
        float4 t = *(const float4*)(g_qkv + base + 2 * NDM);
        float d0 = ca * t.x - sa * t.y, d1 = sa * t.x + ca * t.y;
        float d2 = cb * t.z - sb * t.w, d3 = sb * t.z + cb * t.w;
        float4 o;
        o.x = Pm[0]  * d0 + Pm[1]  * d1 + Pm[2]  * d2 + Pm[3]  * d3;
        o.y = Pm[4]  * d0 + Pm[5]  * d1 + Pm[6]  * d2 + Pm[7]  * d3;
        o.z = Pm[8]  * d0 + Pm[9]  * d1 + Pm[10] * d2 + Pm[11] * d3;
        o.w = Pm[12] * d0 + Pm[13] * d1 + Pm[14] * d2 + Pm[15] * d3;
        uint2 uh, ul; split4(o, uh, ul);
        ((uint2*)g_vh)[ob2] = uh; ((uint2*)g_vl)[ob2] = ul;
    }
}

// ---------------- flash attention (bf16x3 wmma, BM=64, BN=64, pre-split) -------
#define FST 72
#define FL_T  (64 * FST)

#define OFF_KH 0
#define OFF_KL (OFF_KH + FL_T)
#define OFF_VH (OFF_KL + FL_T)
#define OFF_VL (OFF_VH + FL_T)
#define OFF_QH (OFF_VL + FL_T)    // reused as P_hi after Q fragments preloaded
#define OFF_QL (OFF_QH + FL_T)    // reused as P_lo
#define BF_ELEMS (OFF_QL + FL_T)

#define FLASH_SMEM (BF_ELEMS * 2 + (2 * FL_T + 128) * 4)

__global__ void __launch_bounds__(256, 2) k_flash() {
    extern __shared__ char fshraw[];
    bf16*  bfb  = (bf16*)fshraw;
    float* Ss   = (float*)(fshraw + BF_ELEMS * 2);
    float* Os   = Ss + FL_T;
    float* m_sm = Os + FL_T;
    float* l_sm = m_sm + 64;

    bf16* Ks_h = bfb + OFF_KH; bf16* Ks_l = bfb + OFF_KL;
    bf16* Vs_h = bfb + OFF_VH; bf16* Vs_l = bfb + OFF_VL;
    bf16* Qs_h = bfb + OFF_QH; bf16* Qs_l = bfb + OFF_QL;
    bf16* Ps_h = Qs_h;         bf16* Ps_l = Qs_l;

    const int tid = threadIdx.x;
    const int w = tid >> 5;
    const int rg = w >> 1;           // q-row group (16 rows)
    const int half = w & 1;          // 32-col half

    const int bh = blockIdx.y;
    const int q0 = blockIdx.x * 64;

    const size_t tb = (size_t)bh * NL * NDH;
    float* Og = g_oT + tb;

    // staging map: idx = tid + 256*t : rr = idx>>3 (0..63), cc = (idx&7)*8
    const int rr0 = tid >> 3;
    const int cc0 = (tid & 7) * 8;

    // init O, m, l; stage pre-split Q
    for (int i = tid; i < FL_T; i += 256) Os[i] = 0.f;
    if (tid < 64) { m_sm[tid] = -1e30f; l_sm[tid] = 0.f; }
#pragma unroll
    for (int t = 0; t < 2; t++) {
        int rr = rr0 + t * 32;
        size_t go = tb + (size_t)(q0 + rr) * NDH + cc0;
        *(uint4*)&Qs_h[rr * FST + cc0] = *(const uint4*)(g_qh + go);
        *(uint4*)&Qs_l[rr * FST + cc0] = *(const uint4*)(g_ql + go);
    }
    __syncthreads();

    wmma::fragment<wmma::matrix_a, 16, 16, 16, bf16, wmma::row_major> aqh[4], aql[4];
#pragma unroll
    for (int kk = 0; kk < 4; kk++) {
        wmma::load_matrix_sync(aqh[kk], &Qs_h[(rg * 16) * FST + kk * 16], FST);
        wmma::load_matrix_sync(aql[kk], &Qs_l[(rg * 16) * FST + kk * 16], FST);
    }
    __syncthreads();   // Q region free for P reuse

    for (int n0 = 0; n0 < NL; n0 += 64) {
        // stage K/V tile (pre-split, pure copies)
#pragma unroll
        for (int t = 0; t < 2; t++) {
            int rr = rr0 + t * 32;
            size_t go = tb + (size_t)(n0 + rr) * NDH + cc0;
            int so = rr * FST + cc0;
            *(uint4*)&Ks_h[so] = *(const uint4*)(g_kh + go);
            *(uint4*)&Ks_l[so] = *(const uint4*)(g_kl + go);
            *(uint4*)&Vs_h[so] = *(const uint4*)(g_vh + go);
            *(uint4*)&Vs_l[so] = *(const uint4*)(g_vl + go);
        }
        __syncthreads();

        // S = Q K^T (warp: rows rg*16..+16, cols half*32..+32)
        wmma::fragment<wmma::accumulator, 16, 16, 16, float> sfrag[2];
#pragma unroll
        for (int nt = 0; nt < 2; nt++) wmma::fill_fragment(sfrag[nt], 0.f);
#pragma unroll
        for (int kk = 0; kk < 4; kk++) {
#pragma unroll
            for (int nt = 0; nt < 2; nt++) {
                wmma::fragment<wmma::matrix_b, 16, 16, 16, bf16, wmma::col_major> bh, bl;
                int kvrow = half * 32 + nt * 16;
                wmma::load_matrix_sync(bh, &Ks_h[kvrow * FST + kk * 16], FST);
                wmma::load_matrix_sync(bl, &Ks_l[kvrow * FST + kk * 16], FST);
                wmma::mma_sync(sfrag[nt], aqh[kk], bl, sfrag[nt]);
                wmma::mma_sync(sfrag[nt], aql[kk], bh, sfrag[nt]);
                wmma::mma_sync(sfrag[nt], aqh[kk], bh, sfrag[nt]);
            }
        }
#pragma unroll
        for (int nt = 0; nt < 2; nt++)
            wmma::store_matrix_sync(&Ss[(rg * 16) * FST + half * 32 + nt * 16],
                                    sfrag[nt], FST, wmma::mem_row_major);
        __syncthreads();

        // online softmax: 4 threads/row, 16 cols each, vectorized
        {
            int r = tid >> 2;
            int qd = tid & 3;
            float sv[16];
            const float4* sp = (const float4*)&Ss[r * FST + qd * 16];
#pragma unroll
            for (int j = 0; j < 4; j++) *(float4*)&sv[j * 4] = sp[j];
            float mloc = -1e30f;
#pragma unroll
            for (int j = 0; j < 16; j++) {
                sv[j] *= 0.125f;
                mloc = fmaxf(mloc, sv[j]);
            }
            mloc = fmaxf(mloc, __shfl_xor_sync(0xffffffffu, mloc, 1));
            mloc = fmaxf(mloc, __shfl_xor_sync(0xffffffffu, mloc, 2));
            float m_old = m_sm[r];
            float m_new = fmaxf(m_old, mloc);
            float alpha = __expf(m_old - m_new);
            float lsum = 0.f;
            bf16 hh[16], ll[16];
#pragma unroll
            for (int j = 0; j < 16; j++) {
                float p = __expf(sv[j] - m_new);
                lsum += p;
                split_bf16(p, hh[j], ll[j]);
            }
            uint4 uh0, uh1, ul0, ul1;
            uh0.x = pack2(hh[0], hh[1]);  uh0.y = pack2(hh[2], hh[3]);
            uh0.z = pack2(hh[4], hh[5]);  uh0.w = pack2(hh[6], hh[7]);
            uh1.x = pack2(hh[8], hh[9]);  uh1.y = pack2(hh[10], hh[11]);
            uh1.z = pack2(hh[12], hh[13]); uh1.w = pack2(hh[14], hh[15]);
            ul0.x = pack2(ll[0], ll[1]);  ul0.y = pack2(ll[2], ll[3]);
            ul0.z = pack2(ll[4], ll[5]);  ul0.w = pack2(ll[6], ll[7]);
            ul1.x = pack2(ll[8], ll[9]);  ul1.y = pack2(ll[10], ll[11]);
            ul1.z = pack2(ll[12], ll[13]); ul1.w = pack2(ll[14], ll[15]);
            *(uint4*)&Ps_h[r * FST + qd * 16]     = uh0;
            *(uint4*)&Ps_h[r * FST + qd * 16 + 8] = uh1;
            *(uint4*)&Ps_l[r * FST + qd * 16]     = ul0;
            *(uint4*)&Ps_l[r * FST + qd * 16 + 8] = ul1;

            lsum += __shfl_xor_sync(0xffffffffu, lsum, 1);
            lsum += __shfl_xor_sync(0xffffffffu, lsum, 2);
            if (qd == 0) {
                m_sm[r] = m_new;
                l_sm[r] = l_sm[r] * alpha + lsum;
            }
            float4* op = (float4*)&Os[r * FST + qd * 16];
#pragma unroll
            for (int j = 0; j < 4; j++) {
                float4 t = op[j];
                t.x *= alpha; t.y *= alpha; t.z *= alpha; t.w *= alpha;
                op[j] = t;
            }
        }
        __syncthreads();

        // O += P V (warp: rows rg*16..+16, d cols half*32..+32)
        wmma::fragment<wmma::accumulator, 16, 16, 16, float> ofrag[2];
#pragma unroll
        for (int nt = 0; nt < 2; nt++)
            wmma::load_matrix_sync(ofrag[nt], &Os[(rg * 16) * FST + half * 32 + nt * 16],
                                   FST, wmma::mem_row_major);
#pragma unroll
        for (int kk = 0; kk < 4; kk++) {
            wmma::fragment<wmma::matrix_a, 16, 16, 16, bf16, wmma::row_major> aph, apl;
            wmma::load_matrix_sync(aph, &Ps_h[(rg * 16) * FST + kk * 16], FST);
            wmma::load_matrix_sync(apl, &Ps_l[(rg * 16) * FST + kk * 16], FST);
#pragma unroll
            for (int nt = 0; nt < 2; nt++) {
                wmma::fragment<wmma::matrix_b, 16, 16, 16, bf16, wmma::row_major> vh, vl;
                int dcol = half * 32 + nt * 16;
                wmma::load_matrix_sync(vh, &Vs_h[(kk * 16) * FST + dcol], FST);
                wmma::load_matrix_sync(vl, &Vs_l[(kk * 16) * FST + dcol], FST);
                wmma::mma_sync(ofrag[nt], aph, vl, ofrag[nt]);
                wmma::mma_sync(ofrag[nt], apl, vh, ofrag[nt]);
                wmma::mma_sync(ofrag[nt], aph, vh, ofrag[nt]);
            }
        }
#pragma unroll
        for (int nt = 0; nt < 2; nt++)
            wmma::store_matrix_sync(&Os[(rg * 16) * FST + half * 32 + nt * 16],
                                    ofrag[nt], FST, wmma::mem_row_major);
        __syncthreads();
    }

    // normalize and write out
    for (int i = tid; i < 64 * 16; i += 256) {
        int rr = i >> 4, cc = (i & 15) << 2;
        float inv = 1.f / l_sm[rr];
        float4 ov = *(float4*)&Os[rr * FST + cc];
        ov.x *= inv; ov.y *= inv; ov.z *= inv; ov.w *= inv;
        *(float4*)(Og + (size_t)(q0 + rr) * NDH + cc) = ov;
    }
}

// ---------------- apply Mo; emit pre-split oTok --------------------------------
__global__ void k_transform_o() {
    int idx = blockIdx.x * blockDim.x + threadIdx.x;
    if (idx >= NB * NH * NL * NG) return;
    int g = idx & 15;
    int l = (idx >> 4) & (NL - 1);
    int h = (idx >> 15) & 15;
    int b = idx >> 19;
    int c = l >> 8, p = l & 255;
    const float* Pi = g_Pi + (b * NC + c) * 16;
    float4 dv = *(const float4*)(g_Dt + (p * NG + g) * 4);
    float ca = dv.x, sa = dv.y, cb = dv.z, sb = dv.w;

    float4 t = *(const float4*)(g_oT + ((size_t)(b * NH + h) * NL + l) * NDH + g * 4);
    float z0 = Pi[0]  * t.x + Pi[1]  * t.y + Pi[2]  * t.z + Pi[3]  * t.w;
    float z1 = Pi[4]  * t.x + Pi[5]  * t.y + Pi[6]  * t.z + Pi[7]  * t.w;
    float z2 = Pi[8]  * t.x + Pi[9]  * t.y + Pi[10] * t.z + Pi[11] * t.w;
    float z3 = Pi[12] * t.x + Pi[13] * t.y + Pi[14] * t.z + Pi[15] * t.w;
    float4 o;
    o.x =  ca * z0 + sa * z1;
    o.y = -sa * z0 + ca * z1;
    o.z =  cb * z2 + sb * z3;
    o.w = -sb * z2 + cb * z3;
    size_t ob2 = ((size_t)(b * NL + l) * NDM + h * NDH + g * 4) >> 2;
    uint2 uh, ul; split4(o, uh, ul);
    ((uint2*)g_oh)[ob2] = uh; ((uint2*)g_ol)[ob2] = ul;
}

// ---------------- launch --------------------------------------------------------
extern "C" void kernel_launch(void* const* d_in, const int* in_sizes, int n_in,
                              void* d_out, int out_size) {
    (void)in_sizes; (void)n_in; (void)out_size;
    const float* x     = (const float*)d_in[0];
    const float* vm    = (const float*)d_in[1];
    const float* Km    = (const float*)d_in[2];
    const float* wqkv  = (const float*)d_in[3];
    const float* wproj = (const float*)d_in[4];
    float* out = (float*)d_out;

    cudaFuncSetAttribute(k_flash, cudaFuncAttributeMaxDynamicSharedMemorySize, FLASH_SMEM);

    bf16 *xh, *xl, *wqh, *wql, *wph, *wpl;
    cudaGetSymbolAddress((void**)&xh, g_xh);   cudaGetSymbolAddress((void**)&xl, g_xl);
    cudaGetSymbolAddress((void**)&wqh, g_wqh); cudaGetSymbolAddress((void**)&wql, g_wql);
    cudaGetSymbolAddress((void**)&wph, g_wph); cudaGetSymbolAddress((void**)&wpl, g_wpl);

    prope_mats<<<1, 32>>>(vm, Km);
    prope_dtab<<<16, 256>>>();
    k_split<<<(NB * NL * NDM / 4 + 255) / 256, 256>>>(x, xh, xl, NB * NL * NDM / 4);
    k_split<<<(3 * NDM * NDM / 4 + 255) / 256, 256>>>(wqkv, wqh, wql, 3 * NDM * NDM / 4);
    k_split<<<(NDM * NDM / 4 + 255) / 256, 256>>>(wproj, wph, wpl, NDM * NDM / 4);
    k_gemm_qkv<<<dim3(3 * NDM / 128, NB * NL / 128), 256>>>();
    k_transform_qkv<<<(NB * NH * NL * NG) / 256, 256>>>();
    k_flash<<<dim3(NL / 64, NB * NH), 256, FLASH_SMEM>>>();
    k_transform_o<<<(NB * NH * NL * NG) / 256, 256>>>();
    k_gemm_proj<<<dim3(NDM / 128, NB * NL / 128), 256>>>(out);
}